// round 2
// baseline (speedup 1.0000x reference)
#include <cuda_runtime.h>
#include <math.h>
#include <stdint.h>

// Problem constants
#define ED 128
#define LH 128
#define HD 64
#define NG 512            // 4*LH
#define N_AB 300
#define N_MV 900
#define MAXB 4096

// -------- scratch (device globals; no allocations allowed) --------
__device__ float g_num[MAXB * ED];                  // numerical @ num_W^T + num_b   [B,128]
__device__ float g_gates[(size_t)MAXB * NG];        // gates partial (num + hh parts) [B,512]
__device__ float g_tab_ab[12 * N_AB * NG];          // per-slot ability tables  (7.4 MB)
__device__ float g_tab_mv[48 * N_MV * NG];          // per-slot move tables     (88.5 MB)

// ---------------------------------------------------------------------------
// Generic C[r,c] (+)= sum_k A[r,k] * W[c, wColBase + z*wColStepZ + k] (+ bias[c])
// Tiles: BM=BN=64, BK=32, 256 threads, 4x4 register microtile per thread.
// z dimension reuses A, offsets W columns and C rows (for per-slot tables).
// ---------------------------------------------------------------------------
#define BM 64
#define BN 64
#define BK 32

__global__ void gemm_nt_kernel(const float* __restrict__ A, int lda,
                               const float* __restrict__ W, int ldw,
                               int wColBase, int wColStepZ,
                               float* __restrict__ C, int ldc, int cRowsPerZ,
                               int N, int K,
                               const float* __restrict__ bias, int accumulate)
{
    __shared__ float As[BK][BM + 1];
    __shared__ float Bs[BK][BN + 1];

    const int z = blockIdx.z;
    const int M = cRowsPerZ;
    const float* Wz = W + (size_t)wColBase + (size_t)z * wColStepZ;
    float* Cz = C + (size_t)z * (size_t)cRowsPerZ * ldc;

    const int row0 = blockIdx.y * BM;
    const int col0 = blockIdx.x * BN;
    const int t  = threadIdx.x;          // 0..255
    const int tx = t & 15;               // col group
    const int ty = t >> 4;               // row group

    float acc[4][4];
#pragma unroll
    for (int i = 0; i < 4; i++)
#pragma unroll
        for (int j = 0; j < 4; j++) acc[i][j] = 0.f;

    const int lm = t >> 2;               // 0..63 : tile row / tile col for loading
    const int ks = (t & 3) * 8;          // 0,8,16,24 : k segment start

    for (int k0 = 0; k0 < K; k0 += BK) {
        // load A tile (64 rows x 32 k), zero-padded
        {
            const int gr = row0 + lm;
            const bool rok = (gr < M);
            const size_t base = (size_t)gr * lda + k0 + ks;
#pragma unroll
            for (int i = 0; i < 8; i++) {
                const int k = k0 + ks + i;
                As[ks + i][lm] = (rok && k < K) ? A[base + i] : 0.f;
            }
        }
        // load W tile (64 cols x 32 k), zero-padded
        {
            const int gc = col0 + lm;
            const bool cok = (gc < N);
            const size_t base = (size_t)gc * ldw + k0 + ks;
#pragma unroll
            for (int i = 0; i < 8; i++) {
                const int k = k0 + ks + i;
                Bs[ks + i][lm] = (cok && k < K) ? Wz[base + i] : 0.f;
            }
        }
        __syncthreads();

#pragma unroll
        for (int kk = 0; kk < BK; kk++) {
            float a[4], b[4];
#pragma unroll
            for (int i = 0; i < 4; i++) a[i] = As[kk][ty * 4 + i];
#pragma unroll
            for (int i = 0; i < 4; i++) b[i] = Bs[kk][tx * 4 + i];
#pragma unroll
            for (int i = 0; i < 4; i++)
#pragma unroll
                for (int j = 0; j < 4; j++)
                    acc[i][j] += a[i] * b[j];
        }
        __syncthreads();
    }

#pragma unroll
    for (int i = 0; i < 4; i++) {
        const int r = row0 + ty * 4 + i;
        if (r >= M) continue;
#pragma unroll
        for (int j = 0; j < 4; j++) {
            const int c = col0 + tx * 4 + j;
            if (c >= N) continue;
            float v = acc[i][j];
            if (bias) v += bias[c];
            const size_t idx = (size_t)r * ldc + c;
            Cz[idx] = accumulate ? (Cz[idx] + v) : v;
        }
    }
}

// ---------------------------------------------------------------------------
// Fused tail: gather table rows -> gates -> LSTM -> MLP -> softmax/mask.
// One block per batch row, 512 threads (thread j owns gate j).
// ---------------------------------------------------------------------------
__global__ void fused_tail_kernel(const int* __restrict__ ability_ids,
                                  const int* __restrict__ move_ids,
                                  const float* __restrict__ c0,
                                  const float* __restrict__ mask,
                                  const float* __restrict__ bih,
                                  const float* __restrict__ bhh,
                                  const float* __restrict__ W1,
                                  const float* __restrict__ b1,
                                  const float* __restrict__ W2,
                                  const float* __restrict__ b2,
                                  const float* __restrict__ Wa,
                                  const float* __restrict__ ba,
                                  float* __restrict__ out, int B)
{
    __shared__ int   s_aid[12];
    __shared__ int   s_mid[48];
    __shared__ float s_g[NG];
    __shared__ float s_h1[LH];
    __shared__ float s_t1[HD];
    __shared__ float s_feat[ED];
    __shared__ float s_logits[9];

    const int b = blockIdx.x;
    const int j = threadIdx.x;

    if (j < 12)      s_aid[j]      = ability_ids[b * 12 + j];
    else if (j < 60) s_mid[j - 12] = move_ids[b * 48 + (j - 12)];
    __syncthreads();

    // gate accumulation
    float acc = g_gates[(size_t)b * NG + j] + bih[j] + bhh[j];
#pragma unroll
    for (int s = 0; s < 12; s++)
        acc += g_tab_ab[((size_t)(s * N_AB + s_aid[s])) * NG + j];
#pragma unroll
    for (int s = 0; s < 48; s++)
        acc += g_tab_mv[((size_t)(s * N_MV + s_mid[s])) * NG + j];
    s_g[j] = acc;
    __syncthreads();

    // LSTM cell (torch gate order i,f,g,o)
    if (j < LH) {
        const float iv = 1.f / (1.f + expf(-s_g[j]));
        const float fv = 1.f / (1.f + expf(-s_g[LH + j]));
        const float gv = tanhf(s_g[2 * LH + j]);
        const float ov = 1.f / (1.f + expf(-s_g[3 * LH + j]));
        const float c1 = fv * c0[(size_t)b * LH + j] + iv * gv;
        const float h1 = ov * tanhf(c1);
        s_h1[j] = h1;
        out[(size_t)B * 9 + (size_t)b * LH + j] = h1;
        out[(size_t)B * 9 + (size_t)B * LH + (size_t)b * LH + j] = c1;
    }
    __syncthreads();

    // MLP: t1 = relu(h1 @ W1^T + b1)
    if (j < HD) {
        float a = b1[j];
#pragma unroll
        for (int t = 0; t < LH; t++) a += W1[j * LH + t] * s_h1[t];
        s_t1[j] = fmaxf(a, 0.f);
    }
    __syncthreads();

    // feat = t1 @ W2^T + b2
    if (j < ED) {
        float a = b2[j];
#pragma unroll
        for (int t = 0; t < HD; t++) a += W2[j * HD + t] * s_t1[t];
        s_feat[j] = a;
    }
    __syncthreads();

    // logits = feat @ Wa^T + ba
    if (j < 9) {
        float a = ba[j];
#pragma unroll
        for (int t = 0; t < ED; t++) a += Wa[j * ED + t] * s_feat[t];
        s_logits[j] = a;
    }
    __syncthreads();

    // softmax + masked renormalization (single thread; 9 elements)
    if (j == 0) {
        float mx = s_logits[0];
#pragma unroll
        for (int a = 1; a < 9; a++) mx = fmaxf(mx, s_logits[a]);
        float p[9], sum = 0.f;
#pragma unroll
        for (int a = 0; a < 9; a++) { p[a] = expf(s_logits[a] - mx); sum += p[a]; }
        float pm[9], msum = 0.f;
#pragma unroll
        for (int a = 0; a < 9; a++) {
            p[a] /= sum;
            pm[a] = p[a] * mask[(size_t)b * 9 + a];
            msum += pm[a];
        }
#pragma unroll
        for (int a = 0; a < 9; a++)
            out[(size_t)b * 9 + a] = (msum > 0.f) ? (pm[a] / msum) : p[a];
    }
}

// ---------------------------------------------------------------------------
extern "C" void kernel_launch(void* const* d_in, const int* in_sizes, int n_in,
                              void* d_out, int out_size)
{
    const int*   ability_ids = (const int*)  d_in[0];
    const int*   move_ids    = (const int*)  d_in[1];
    const float* numerical   = (const float*)d_in[2];
    const float* mask        = (const float*)d_in[3];
    const float* h0          = (const float*)d_in[4];
    const float* c0          = (const float*)d_in[5];
    const float* ability_emb = (const float*)d_in[6];
    const float* move_emb    = (const float*)d_in[7];
    const float* num_W       = (const float*)d_in[8];
    const float* num_b       = (const float*)d_in[9];
    const float* Wih         = (const float*)d_in[10];
    const float* Whh         = (const float*)d_in[11];
    const float* bih         = (const float*)d_in[12];
    const float* bhh         = (const float*)d_in[13];
    const float* W1          = (const float*)d_in[14];
    const float* b1          = (const float*)d_in[15];
    const float* W2          = (const float*)d_in[16];
    const float* b2          = (const float*)d_in[17];
    const float* Wa          = (const float*)d_in[18];
    const float* ba          = (const float*)d_in[19];

    const int B = in_sizes[0] / 12;   // 4096

    float *p_num, *p_gates, *p_tab_ab, *p_tab_mv;
    cudaGetSymbolAddress((void**)&p_num,    g_num);
    cudaGetSymbolAddress((void**)&p_gates,  g_gates);
    cudaGetSymbolAddress((void**)&p_tab_ab, g_tab_ab);
    cudaGetSymbolAddress((void**)&p_tab_mv, g_tab_mv);

    dim3 blk(256);

    // 1) num = numerical @ num_W^T + num_b          [B,128], K=84
    gemm_nt_kernel<<<dim3(2, (B + BM - 1) / BM, 1), blk>>>(
        numerical, 84, num_W, 84, 0, 0, p_num, ED, B, ED, 84, num_b, 0);

    // 2) gates = num @ Wih[:,7680:7808]^T           [B,512], K=128
    gemm_nt_kernel<<<dim3(8, (B + BM - 1) / BM, 1), blk>>>(
        p_num, ED, Wih, 7808, 7680, 0, p_gates, NG, B, NG, ED, nullptr, 0);

    // 3) gates += h0 @ Whh^T                        [B,512], K=128
    gemm_nt_kernel<<<dim3(8, (B + BM - 1) / BM, 1), blk>>>(
        h0, LH, Whh, LH, 0, 0, p_gates, NG, B, NG, LH, nullptr, 1);

    // 4) ability tables: z = slot 0..11, W cols at z*128, K=128
    gemm_nt_kernel<<<dim3(8, (N_AB + BM - 1) / BM, 12), blk>>>(
        ability_emb, ED, Wih, 7808, 0, ED, p_tab_ab, NG, N_AB, NG, ED, nullptr, 0);

    // 5) move tables: z = slot 0..47, W cols at 1536 + z*128, K=128
    gemm_nt_kernel<<<dim3(8, (N_MV + BM - 1) / BM, 48), blk>>>(
        move_emb, ED, Wih, 7808, 1536, ED, p_tab_mv, NG, N_MV, NG, ED, nullptr, 0);

    // 6) fused gather + LSTM + MLP + masked softmax
    fused_tail_kernel<<<B, 512>>>(ability_ids, move_ids, c0, mask,
                                  bih, bhh, W1, b1, W2, b2, Wa, ba,
                                  (float*)d_out, B);
}

// round 4
// speedup vs baseline: 1.2565x; 1.2565x over previous
#include <cuda_runtime.h>
#include <math.h>
#include <stdint.h>

// Problem constants
#define ED 128
#define LH 128
#define HD 64
#define NG 512            // 4*LH
#define N_AB 300
#define N_MV 900
#define MAXB 4096

// -------- scratch (device globals; no allocations allowed) --------
__device__ float g_num[MAXB * ED];                  // numerical @ num_W^T + num_b   [B,128]
__device__ float g_gates[(size_t)MAXB * NG];        // gates partial (num + hh)      [B,512]
__device__ float g_tab_ab[12 * N_AB * NG];          // per-slot ability tables  (7.4 MB)
__device__ float g_tab_mv[48 * N_MV * NG];          // per-slot move tables     (88.5 MB)

// ---------------------------------------------------------------------------
// Fast SGEMM: C[r,c] (+)= sum_k A[r,k] * W[c, wColBase + z*wColStepZ + k] (+bias)
// 128x128 tile, BK=8, 256 threads, 8x8 microtile, float4 everywhere.
// Requirements: N (grid.x*128) cols all valid, K % 8 == 0, ldc % 4 == 0,
//               A/W 16B-aligned rows (lda,ldw % 4 == 0). M can be ragged.
// ---------------------------------------------------------------------------
__global__ __launch_bounds__(256, 2)
void sgemm128_nt(const float* __restrict__ A, int lda, int M,
                 const float* __restrict__ W, int ldw, int wColBase, int wColStepZ,
                 float* __restrict__ C, int ldc, int cRowsPerZ,
                 int K, const float* __restrict__ bias, int accumulate)
{
    __shared__ float As[8][128];
    __shared__ float Bs[8][128];

    const int z = blockIdx.z;
    const float* Wz = W + (size_t)wColBase + (size_t)z * wColStepZ;
    float* Cz = C + (size_t)z * (size_t)cRowsPerZ * ldc;

    const int row0 = blockIdx.y * 128;
    const int col0 = blockIdx.x * 128;
    const int t  = threadIdx.x;          // 0..255
    const int tx = t & 15;               // 0..15
    const int ty = t >> 4;               // 0..15

    const int lr = t >> 1;               // 0..127 tile row/col for loading
    const int lc = (t & 1) * 4;          // 0 or 4

    float acc[8][8];
#pragma unroll
    for (int i = 0; i < 8; i++)
#pragma unroll
        for (int j = 0; j < 8; j++) acc[i][j] = 0.f;

    for (int k0 = 0; k0 < K; k0 += 8) {
        // A tile: 128 rows x 8 k, transposed into As[k][row]
        {
            const int gr = row0 + lr;
            float4 v = make_float4(0.f, 0.f, 0.f, 0.f);
            if (gr < M) v = *(const float4*)(A + (size_t)gr * lda + k0 + lc);
            As[lc + 0][lr] = v.x; As[lc + 1][lr] = v.y;
            As[lc + 2][lr] = v.z; As[lc + 3][lr] = v.w;
        }
        // W tile: 128 output-cols x 8 k, transposed into Bs[k][col]
        {
            const int gc = col0 + lr;
            float4 v = *(const float4*)(Wz + (size_t)gc * ldw + k0 + lc);
            Bs[lc + 0][lr] = v.x; Bs[lc + 1][lr] = v.y;
            Bs[lc + 2][lr] = v.z; Bs[lc + 3][lr] = v.w;
        }
        __syncthreads();

#pragma unroll
        for (int kk = 0; kk < 8; kk++) {
            const float4 a0 = *(const float4*)&As[kk][ty * 4];
            const float4 a1 = *(const float4*)&As[kk][ty * 4 + 64];
            const float4 b0 = *(const float4*)&Bs[kk][tx * 4];
            const float4 b1 = *(const float4*)&Bs[kk][tx * 4 + 64];
            const float a[8] = {a0.x, a0.y, a0.z, a0.w, a1.x, a1.y, a1.z, a1.w};
            const float b[8] = {b0.x, b0.y, b0.z, b0.w, b1.x, b1.y, b1.z, b1.w};
#pragma unroll
            for (int i = 0; i < 8; i++)
#pragma unroll
                for (int j = 0; j < 8; j++)
                    acc[i][j] += a[i] * b[j];
        }
        __syncthreads();
    }

    // Epilogue: rows ty*4 + {0..3} (+64), cols tx*4 + {0..3} (+64)
#pragma unroll
    for (int ih = 0; ih < 2; ih++) {
#pragma unroll
        for (int i = 0; i < 4; i++) {
            const int r = row0 + ty * 4 + ih * 64 + i;
            if (r >= M) continue;
            const int ii = ih * 4 + i;
#pragma unroll
            for (int jh = 0; jh < 2; jh++) {
                const int c = col0 + tx * 4 + jh * 64;
                const int jj = jh * 4;
                float4 v;
                v.x = acc[ii][jj + 0]; v.y = acc[ii][jj + 1];
                v.z = acc[ii][jj + 2]; v.w = acc[ii][jj + 3];
                if (bias) {
                    v.x += bias[c + 0]; v.y += bias[c + 1];
                    v.z += bias[c + 2]; v.w += bias[c + 3];
                }
                float* p = Cz + (size_t)r * ldc + c;
                if (accumulate) {
                    const float4 o = *(const float4*)p;
                    v.x += o.x; v.y += o.y; v.z += o.z; v.w += o.w;
                }
                *(float4*)p = v;
            }
        }
    }
}

// ---------------------------------------------------------------------------
// Small GEMM for the num projection (K=84, not multiple of 8). 64x64x32 tiles.
// ---------------------------------------------------------------------------
#define BM 64
#define BN 64
#define BK 32

__global__ void gemm_nt_kernel(const float* __restrict__ A, int lda,
                               const float* __restrict__ W, int ldw,
                               float* __restrict__ C, int ldc, int M,
                               int N, int K,
                               const float* __restrict__ bias)
{
    __shared__ float As[BK][BM + 1];
    __shared__ float Bs[BK][BN + 1];

    const int row0 = blockIdx.y * BM;
    const int col0 = blockIdx.x * BN;
    const int t  = threadIdx.x;
    const int tx = t & 15;
    const int ty = t >> 4;

    float acc[4][4];
#pragma unroll
    for (int i = 0; i < 4; i++)
#pragma unroll
        for (int j = 0; j < 4; j++) acc[i][j] = 0.f;

    const int lm = t >> 2;
    const int ks = (t & 3) * 8;

    for (int k0 = 0; k0 < K; k0 += BK) {
        {
            const int gr = row0 + lm;
            const bool rok = (gr < M);
            const size_t base = (size_t)gr * lda + k0 + ks;
#pragma unroll
            for (int i = 0; i < 8; i++) {
                const int k = k0 + ks + i;
                As[ks + i][lm] = (rok && k < K) ? A[base + i] : 0.f;
            }
        }
        {
            const int gc = col0 + lm;
            const bool cok = (gc < N);
            const size_t base = (size_t)gc * ldw + k0 + ks;
#pragma unroll
            for (int i = 0; i < 8; i++) {
                const int k = k0 + ks + i;
                Bs[ks + i][lm] = (cok && k < K) ? W[base + i] : 0.f;
            }
        }
        __syncthreads();

#pragma unroll
        for (int kk = 0; kk < BK; kk++) {
            float a[4], b[4];
#pragma unroll
            for (int i = 0; i < 4; i++) a[i] = As[kk][ty * 4 + i];
#pragma unroll
            for (int i = 0; i < 4; i++) b[i] = Bs[kk][tx * 4 + i];
#pragma unroll
            for (int i = 0; i < 4; i++)
#pragma unroll
                for (int j = 0; j < 4; j++)
                    acc[i][j] += a[i] * b[j];
        }
        __syncthreads();
    }

#pragma unroll
    for (int i = 0; i < 4; i++) {
        const int r = row0 + ty * 4 + i;
        if (r >= M) continue;
#pragma unroll
        for (int j = 0; j < 4; j++) {
            const int c = col0 + tx * 4 + j;
            if (c >= N) continue;
            float v = acc[i][j];
            if (bias) v += bias[c];
            C[(size_t)r * ldc + c] = v;
        }
    }
}

// ---------------------------------------------------------------------------
// Fused tail: gather table rows -> gates -> LSTM -> MLP -> softmax/mask.
// One block per batch row, 512 threads (thread j owns gate j).
// ---------------------------------------------------------------------------
__global__ void fused_tail_kernel(const int* __restrict__ ability_ids,
                                  const int* __restrict__ move_ids,
                                  const float* __restrict__ c0,
                                  const float* __restrict__ mask,
                                  const float* __restrict__ bih,
                                  const float* __restrict__ bhh,
                                  const float* __restrict__ W1,
                                  const float* __restrict__ b1,
                                  const float* __restrict__ W2,
                                  const float* __restrict__ b2,
                                  const float* __restrict__ Wa,
                                  const float* __restrict__ ba,
                                  float* __restrict__ out, int B)
{
    __shared__ int   s_aid[12];
    __shared__ int   s_mid[48];
    __shared__ float s_g[NG];
    __shared__ float s_h1[LH];
    __shared__ float s_t1[HD];
    __shared__ float s_feat[ED];
    __shared__ float s_logits[9];

    const int b = blockIdx.x;
    const int j = threadIdx.x;

    if (j < 12)      s_aid[j]      = ability_ids[b * 12 + j];
    else if (j < 60) s_mid[j - 12] = move_ids[b * 48 + (j - 12)];
    __syncthreads();

    // gate accumulation
    float acc = g_gates[(size_t)b * NG + j] + bih[j] + bhh[j];
#pragma unroll
    for (int s = 0; s < 12; s++)
        acc += g_tab_ab[((size_t)(s * N_AB + s_aid[s])) * NG + j];
#pragma unroll
    for (int s = 0; s < 48; s++)
        acc += g_tab_mv[((size_t)(s * N_MV + s_mid[s])) * NG + j];
    s_g[j] = acc;
    __syncthreads();

    // LSTM cell (torch gate order i,f,g,o)
    if (j < LH) {
        const float iv = 1.f / (1.f + expf(-s_g[j]));
        const float fv = 1.f / (1.f + expf(-s_g[LH + j]));
        const float gv = tanhf(s_g[2 * LH + j]);
        const float ov = 1.f / (1.f + expf(-s_g[3 * LH + j]));
        const float c1 = fv * c0[(size_t)b * LH + j] + iv * gv;
        const float h1 = ov * tanhf(c1);
        s_h1[j] = h1;
        out[(size_t)B * 9 + (size_t)b * LH + j] = h1;
        out[(size_t)B * 9 + (size_t)B * LH + (size_t)b * LH + j] = c1;
    }
    __syncthreads();

    // MLP: t1 = relu(h1 @ W1^T + b1)
    if (j < HD) {
        float a = b1[j];
#pragma unroll
        for (int t = 0; t < LH; t++) a += W1[j * LH + t] * s_h1[t];
        s_t1[j] = fmaxf(a, 0.f);
    }
    __syncthreads();

    // feat = t1 @ W2^T + b2
    if (j < ED) {
        float a = b2[j];
#pragma unroll
        for (int t = 0; t < HD; t++) a += W2[j * HD + t] * s_t1[t];
        s_feat[j] = a;
    }
    __syncthreads();

    // logits = feat @ Wa^T + ba
    if (j < 9) {
        float a = ba[j];
#pragma unroll
        for (int t = 0; t < ED; t++) a += Wa[j * ED + t] * s_feat[t];
        s_logits[j] = a;
    }
    __syncthreads();

    // softmax + masked renormalization
    if (j == 0) {
        float mx = s_logits[0];
#pragma unroll
        for (int a = 1; a < 9; a++) mx = fmaxf(mx, s_logits[a]);
        float p[9], sum = 0.f;
#pragma unroll
        for (int a = 0; a < 9; a++) { p[a] = expf(s_logits[a] - mx); sum += p[a]; }
        float pm[9], msum = 0.f;
#pragma unroll
        for (int a = 0; a < 9; a++) {
            p[a] /= sum;
            pm[a] = p[a] * mask[(size_t)b * 9 + a];
            msum += pm[a];
        }
#pragma unroll
        for (int a = 0; a < 9; a++)
            out[(size_t)b * 9 + a] = (msum > 0.f) ? (pm[a] / msum) : p[a];
    }
}

// ---------------------------------------------------------------------------
extern "C" void kernel_launch(void* const* d_in, const int* in_sizes, int n_in,
                              void* d_out, int out_size)
{
    const int*   ability_ids = (const int*)  d_in[0];
    const int*   move_ids    = (const int*)  d_in[1];
    const float* numerical   = (const float*)d_in[2];
    const float* mask        = (const float*)d_in[3];
    const float* h0          = (const float*)d_in[4];
    const float* c0          = (const float*)d_in[5];
    const float* ability_emb = (const float*)d_in[6];
    const float* move_emb    = (const float*)d_in[7];
    const float* num_W       = (const float*)d_in[8];
    const float* num_b       = (const float*)d_in[9];
    const float* Wih         = (const float*)d_in[10];
    const float* Whh         = (const float*)d_in[11];
    const float* bih         = (const float*)d_in[12];
    const float* bhh         = (const float*)d_in[13];
    const float* W1          = (const float*)d_in[14];
    const float* b1          = (const float*)d_in[15];
    const float* W2          = (const float*)d_in[16];
    const float* b2          = (const float*)d_in[17];
    const float* Wa          = (const float*)d_in[18];
    const float* ba          = (const float*)d_in[19];

    const int B = in_sizes[0] / 12;   // 4096

    float *p_num, *p_gates, *p_tab_ab, *p_tab_mv;
    cudaGetSymbolAddress((void**)&p_num,    g_num);
    cudaGetSymbolAddress((void**)&p_gates,  g_gates);
    cudaGetSymbolAddress((void**)&p_tab_ab, g_tab_ab);
    cudaGetSymbolAddress((void**)&p_tab_mv, g_tab_mv);

    // 1) num = numerical @ num_W^T + num_b      [B,128], K=84 (small kernel)
    gemm_nt_kernel<<<dim3(2, (B + BM - 1) / BM, 1), 256>>>(
        numerical, 84, num_W, 84, p_num, ED, B, ED, 84, num_b);

    // 2) gates = num @ Wih[:,7680:7808]^T       [B,512], K=128
    sgemm128_nt<<<dim3(NG / 128, B / 128, 1), 256>>>(
        p_num, ED, B, Wih, 7808, 7680, 0, p_gates, NG, B, ED, nullptr, 0);

    // 3) gates += h0 @ Whh^T                    [B,512], K=128
    sgemm128_nt<<<dim3(NG / 128, B / 128, 1), 256>>>(
        h0, LH, B, Whh, LH, 0, 0, p_gates, NG, B, LH, nullptr, 1);

    // 4) ability tables: z = 0..11, W cols at z*128      [300,512] each
    sgemm128_nt<<<dim3(NG / 128, (N_AB + 127) / 128, 12), 256>>>(
        ability_emb, ED, N_AB, Wih, 7808, 0, ED, p_tab_ab, NG, N_AB, ED, nullptr, 0);

    // 5) move tables: z = 0..47, W cols at 1536 + z*128  [900,512] each
    sgemm128_nt<<<dim3(NG / 128, (N_MV + 127) / 128, 48), 256>>>(
        move_emb, ED, N_MV, Wih, 7808, 1536, ED, p_tab_mv, NG, N_MV, ED, nullptr, 0);

    // 6) fused gather + LSTM + MLP + masked softmax
    fused_tail_kernel<<<B, 512>>>(ability_ids, move_ids, c0, mask,
                                  bih, bhh, W1, b1, W2, b2, Wa, ba,
                                  (float*)d_out, B);
}

// round 6
// speedup vs baseline: 1.4780x; 1.1763x over previous
#include <cuda_runtime.h>
#include <math.h>
#include <stdint.h>

// Problem constants
#define ED 128
#define LH 128
#define HD 64
#define NG 512            // 4*LH
#define N_AB 300
#define N_MV 900
#define MAXB 4096

// -------- scratch (device globals; no allocations allowed) --------
__device__ float g_num[MAXB * ED];                  // numerical @ num_W^T + num_b   [B,128]
__device__ float g_gates[(size_t)MAXB * NG];        // gates partial (num + hh)      [B,512]
__device__ float g_tab_ab[12 * N_AB * NG];          // per-slot ability tables  (7.4 MB)
__device__ float g_tab_mv[48 * N_MV * NG];          // per-slot move tables     (88.5 MB)

__device__ __forceinline__ uint32_t f2tf32(float x) {
    uint32_t r;
    asm("cvt.rna.tf32.f32 %0, %1;" : "=r"(r) : "f"(x));
    return r;
}

// ---------------------------------------------------------------------------
// Tensor-core TF32 GEMM: C[z][r][c] (+)= sum_k A[r,k] * W[c, wColBase+z*step+k]
// CTA tile 128x128, BK=32, 256 threads (8 warps: 4 in M x 2 in N).
// Warp tile 32x64 = 2(m16) x 8(n8) mma.m16n8k8 fragments.
// Requirements: grid.x*128 == N exactly (all cols valid), K % 32 == 0,
//               lda/ldw/ldc % 4 == 0. M ragged OK.
// ---------------------------------------------------------------------------
__global__ __launch_bounds__(256, 2)
void tc_gemm_nt(const float* __restrict__ A, int lda, int M,
                const float* __restrict__ W, int ldw, int wColBase, int wColStepZ,
                float* __restrict__ C, int ldc, int cRowsPerZ,
                int K, int accumulate)
{
    __shared__ __align__(16) float As[128][36];
    __shared__ __align__(16) float Bs[128][36];

    const int z = blockIdx.z;
    const float* Wz = W + (size_t)wColBase + (size_t)z * wColStepZ;
    float* Cz = C + (size_t)z * (size_t)cRowsPerZ * ldc;

    const int row0 = blockIdx.y * 128;
    const int col0 = blockIdx.x * 128;

    const int t    = threadIdx.x;
    const int lane = t & 31;
    const int wid  = t >> 5;
    const int wm   = wid & 3;          // 0..3 : 32-row band
    const int wn   = wid >> 2;         // 0..1 : 64-col band
    const int g    = lane >> 2;        // 0..7
    const int q    = lane & 3;         // 0..3

    const int lr = t >> 1;             // 0..127 load row
    const int lq = t & 1;              // float4 column parity

    float acc[2][8][4];
#pragma unroll
    for (int mi = 0; mi < 2; mi++)
#pragma unroll
        for (int ni = 0; ni < 8; ni++)
#pragma unroll
            for (int r = 0; r < 4; r++) acc[mi][ni][r] = 0.f;

    for (int k0 = 0; k0 < K; k0 += 32) {
        // Load A tile: 128 rows x 32 k (float4 x4 per thread), zero-pad ragged rows
        {
            const int gr = row0 + lr;
            const bool ok = (gr < M);
            const float* src = A + (size_t)gr * lda + k0;
#pragma unroll
            for (int it = 0; it < 4; it++) {
                const int f4 = lq + it * 2;       // 0..7
                float4 v = make_float4(0.f, 0.f, 0.f, 0.f);
                if (ok) v = *(const float4*)(src + f4 * 4);
                *(float4*)&As[lr][f4 * 4] = v;
            }
        }
        // Load W tile: 128 out-cols x 32 k (always valid)
        {
            const int gc = col0 + lr;
            const float* src = Wz + (size_t)gc * ldw + k0;
#pragma unroll
            for (int it = 0; it < 4; it++) {
                const int f4 = lq + it * 2;
                *(float4*)&Bs[lr][f4 * 4] = *(const float4*)(src + f4 * 4);
            }
        }
        __syncthreads();

#pragma unroll
        for (int kk = 0; kk < 4; kk++) {
            const int kb = kk * 8;
            uint32_t af[2][4];
#pragma unroll
            for (int mi = 0; mi < 2; mi++) {
                const int r = wm * 32 + mi * 16 + g;
                af[mi][0] = f2tf32(As[r][kb + q]);
                af[mi][1] = f2tf32(As[r + 8][kb + q]);
                af[mi][2] = f2tf32(As[r][kb + q + 4]);
                af[mi][3] = f2tf32(As[r + 8][kb + q + 4]);
            }
            uint32_t bf[8][2];
#pragma unroll
            for (int ni = 0; ni < 8; ni++) {
                const int c = wn * 64 + ni * 8 + g;
                bf[ni][0] = f2tf32(Bs[c][kb + q]);
                bf[ni][1] = f2tf32(Bs[c][kb + q + 4]);
            }
#pragma unroll
            for (int mi = 0; mi < 2; mi++)
#pragma unroll
                for (int ni = 0; ni < 8; ni++) {
                    asm volatile(
                        "mma.sync.aligned.m16n8k8.row.col.f32.tf32.tf32.f32 "
                        "{%0,%1,%2,%3}, {%4,%5,%6,%7}, {%8,%9}, {%0,%1,%2,%3};"
                        : "+f"(acc[mi][ni][0]), "+f"(acc[mi][ni][1]),
                          "+f"(acc[mi][ni][2]), "+f"(acc[mi][ni][3])
                        : "r"(af[mi][0]), "r"(af[mi][1]), "r"(af[mi][2]), "r"(af[mi][3]),
                          "r"(bf[ni][0]), "r"(bf[ni][1]));
                }
        }
        __syncthreads();
    }

    // Epilogue: c0,c1 at (row, 2q),(row, 2q+1); c2,c3 at (row+8, ...)
#pragma unroll
    for (int mi = 0; mi < 2; mi++) {
        const int rA = row0 + wm * 32 + mi * 16 + g;
        const int rB = rA + 8;
#pragma unroll
        for (int ni = 0; ni < 8; ni++) {
            const int c = col0 + wn * 64 + ni * 8 + q * 2;
            if (rA < M) {
                float2* p = (float2*)(Cz + (size_t)rA * ldc + c);
                float2 v = make_float2(acc[mi][ni][0], acc[mi][ni][1]);
                if (accumulate) { float2 o = *p; v.x += o.x; v.y += o.y; }
                *p = v;
            }
            if (rB < M) {
                float2* p = (float2*)(Cz + (size_t)rB * ldc + c);
                float2 v = make_float2(acc[mi][ni][2], acc[mi][ni][3]);
                if (accumulate) { float2 o = *p; v.x += o.x; v.y += o.y; }
                *p = v;
            }
        }
    }
}

// ---------------------------------------------------------------------------
// Small GEMM for the num projection (K=84). 64x64x32 tiles, fp32 SIMT.
// ---------------------------------------------------------------------------
#define BM 64
#define BN 64
#define BK 32

__global__ void gemm_nt_kernel(const float* __restrict__ A, int lda,
                               const float* __restrict__ W, int ldw,
                               float* __restrict__ C, int ldc, int M,
                               int N, int K,
                               const float* __restrict__ bias)
{
    __shared__ float As[BK][BM + 1];
    __shared__ float Bs[BK][BN + 1];

    const int row0 = blockIdx.y * BM;
    const int col0 = blockIdx.x * BN;
    const int t  = threadIdx.x;
    const int tx = t & 15;
    const int ty = t >> 4;

    float acc[4][4];
#pragma unroll
    for (int i = 0; i < 4; i++)
#pragma unroll
        for (int j = 0; j < 4; j++) acc[i][j] = 0.f;

    const int lm = t >> 2;
    const int ks = (t & 3) * 8;

    for (int k0 = 0; k0 < K; k0 += BK) {
        {
            const int gr = row0 + lm;
            const bool rok = (gr < M);
            const size_t base = (size_t)gr * lda + k0 + ks;
#pragma unroll
            for (int i = 0; i < 8; i++) {
                const int k = k0 + ks + i;
                As[ks + i][lm] = (rok && k < K) ? A[base + i] : 0.f;
            }
        }
        {
            const int gc = col0 + lm;
            const bool cok = (gc < N);
            const size_t base = (size_t)gc * ldw + k0 + ks;
#pragma unroll
            for (int i = 0; i < 8; i++) {
                const int k = k0 + ks + i;
                Bs[ks + i][lm] = (cok && k < K) ? W[base + i] : 0.f;
            }
        }
        __syncthreads();

#pragma unroll
        for (int kk = 0; kk < BK; kk++) {
            float a[4], b[4];
#pragma unroll
            for (int i = 0; i < 4; i++) a[i] = As[kk][ty * 4 + i];
#pragma unroll
            for (int i = 0; i < 4; i++) b[i] = Bs[kk][tx * 4 + i];
#pragma unroll
            for (int i = 0; i < 4; i++)
#pragma unroll
                for (int j = 0; j < 4; j++)
                    acc[i][j] += a[i] * b[j];
        }
        __syncthreads();
    }

#pragma unroll
    for (int i = 0; i < 4; i++) {
        const int r = row0 + ty * 4 + i;
        if (r >= M) continue;
#pragma unroll
        for (int j = 0; j < 4; j++) {
            const int c = col0 + tx * 4 + j;
            if (c >= N) continue;
            float v = acc[i][j];
            if (bias) v += bias[c];
            C[(size_t)r * ldc + c] = v;
        }
    }
}

// ---------------------------------------------------------------------------
// Fused tail: gather table rows -> gates -> LSTM -> MLP -> softmax/mask.
// One block per batch row, 512 threads (thread j owns gate j).
// ---------------------------------------------------------------------------
__global__ void fused_tail_kernel(const int* __restrict__ ability_ids,
                                  const int* __restrict__ move_ids,
                                  const float* __restrict__ c0,
                                  const float* __restrict__ mask,
                                  const float* __restrict__ bih,
                                  const float* __restrict__ bhh,
                                  const float* __restrict__ W1,
                                  const float* __restrict__ b1,
                                  const float* __restrict__ W2,
                                  const float* __restrict__ b2,
                                  const float* __restrict__ Wa,
                                  const float* __restrict__ ba,
                                  float* __restrict__ out, int B)
{
    __shared__ int   s_aid[12];
    __shared__ int   s_mid[48];
    __shared__ float s_g[NG];
    __shared__ float s_h1[LH];
    __shared__ float s_t1[HD];
    __shared__ float s_feat[ED];
    __shared__ float s_logits[9];

    const int b = blockIdx.x;
    const int j = threadIdx.x;

    if (j < 12)      s_aid[j]      = ability_ids[b * 12 + j];
    else if (j < 60) s_mid[j - 12] = move_ids[b * 48 + (j - 12)];
    __syncthreads();

    // gate accumulation
    float acc = g_gates[(size_t)b * NG + j] + bih[j] + bhh[j];
#pragma unroll
    for (int s = 0; s < 12; s++)
        acc += g_tab_ab[((size_t)(s * N_AB + s_aid[s])) * NG + j];
#pragma unroll
    for (int s = 0; s < 48; s++)
        acc += g_tab_mv[((size_t)(s * N_MV + s_mid[s])) * NG + j];
    s_g[j] = acc;
    __syncthreads();

    // LSTM cell (torch gate order i,f,g,o)
    if (j < LH) {
        const float iv = 1.f / (1.f + expf(-s_g[j]));
        const float fv = 1.f / (1.f + expf(-s_g[LH + j]));
        const float gv = tanhf(s_g[2 * LH + j]);
        const float ov = 1.f / (1.f + expf(-s_g[3 * LH + j]));
        const float c1 = fv * c0[(size_t)b * LH + j] + iv * gv;
        const float h1 = ov * tanhf(c1);
        s_h1[j] = h1;
        out[(size_t)B * 9 + (size_t)b * LH + j] = h1;
        out[(size_t)B * 9 + (size_t)B * LH + (size_t)b * LH + j] = c1;
    }
    __syncthreads();

    // MLP: t1 = relu(h1 @ W1^T + b1)
    if (j < HD) {
        float a = b1[j];
#pragma unroll
        for (int t = 0; t < LH; t++) a += W1[j * LH + t] * s_h1[t];
        s_t1[j] = fmaxf(a, 0.f);
    }
    __syncthreads();

    // feat = t1 @ W2^T + b2
    if (j < ED) {
        float a = b2[j];
#pragma unroll
        for (int t = 0; t < HD; t++) a += W2[j * HD + t] * s_t1[t];
        s_feat[j] = a;
    }
    __syncthreads();

    // logits = feat @ Wa^T + ba
    if (j < 9) {
        float a = ba[j];
#pragma unroll
        for (int t = 0; t < ED; t++) a += Wa[j * ED + t] * s_feat[t];
        s_logits[j] = a;
    }
    __syncthreads();

    // softmax + masked renormalization
    if (j == 0) {
        float mx = s_logits[0];
#pragma unroll
        for (int a = 1; a < 9; a++) mx = fmaxf(mx, s_logits[a]);
        float p[9], sum = 0.f;
#pragma unroll
        for (int a = 0; a < 9; a++) { p[a] = expf(s_logits[a] - mx); sum += p[a]; }
        float pm[9], msum = 0.f;
#pragma unroll
        for (int a = 0; a < 9; a++) {
            p[a] /= sum;
            pm[a] = p[a] * mask[(size_t)b * 9 + a];
            msum += pm[a];
        }
#pragma unroll
        for (int a = 0; a < 9; a++)
            out[(size_t)b * 9 + a] = (msum > 0.f) ? (pm[a] / msum) : p[a];
    }
}

// ---------------------------------------------------------------------------
extern "C" void kernel_launch(void* const* d_in, const int* in_sizes, int n_in,
                              void* d_out, int out_size)
{
    const int*   ability_ids = (const int*)  d_in[0];
    const int*   move_ids    = (const int*)  d_in[1];
    const float* numerical   = (const float*)d_in[2];
    const float* mask        = (const float*)d_in[3];
    const float* h0          = (const float*)d_in[4];
    const float* c0          = (const float*)d_in[5];
    const float* ability_emb = (const float*)d_in[6];
    const float* move_emb    = (const float*)d_in[7];
    const float* num_W       = (const float*)d_in[8];
    const float* num_b       = (const float*)d_in[9];
    const float* Wih         = (const float*)d_in[10];
    const float* Whh         = (const float*)d_in[11];
    const float* bih         = (const float*)d_in[12];
    const float* bhh         = (const float*)d_in[13];
    const float* W1          = (const float*)d_in[14];
    const float* b1          = (const float*)d_in[15];
    const float* W2          = (const float*)d_in[16];
    const float* b2          = (const float*)d_in[17];
    const float* Wa          = (const float*)d_in[18];
    const float* ba          = (const float*)d_in[19];

    const int B = in_sizes[0] / 12;   // 4096

    float *p_num, *p_gates, *p_tab_ab, *p_tab_mv;
    cudaGetSymbolAddress((void**)&p_num,    g_num);
    cudaGetSymbolAddress((void**)&p_gates,  g_gates);
    cudaGetSymbolAddress((void**)&p_tab_ab, g_tab_ab);
    cudaGetSymbolAddress((void**)&p_tab_mv, g_tab_mv);

    // 1) num = numerical @ num_W^T + num_b      [B,128], K=84 (SIMT)
    gemm_nt_kernel<<<dim3(2, (B + BM - 1) / BM, 1), 256>>>(
        numerical, 84, num_W, 84, p_num, ED, B, ED, 84, num_b);

    // 2) gates = num @ Wih[:,7680:7808]^T       [B,512], K=128 (TF32 TC)
    tc_gemm_nt<<<dim3(NG / 128, B / 128, 1), 256>>>(
        p_num, ED, B, Wih, 7808, 7680, 0, p_gates, NG, B, ED, 0);

    // 3) gates += h0 @ Whh^T                    [B,512], K=128
    tc_gemm_nt<<<dim3(NG / 128, B / 128, 1), 256>>>(
        h0, LH, B, Whh, LH, 0, 0, p_gates, NG, B, LH, 1);

    // 4) ability tables: z = 0..11, W cols at z*128      [300,512] each
    tc_gemm_nt<<<dim3(NG / 128, (N_AB + 127) / 128, 12), 256>>>(
        ability_emb, ED, N_AB, Wih, 7808, 0, ED, p_tab_ab, NG, N_AB, ED, 0);

    // 5) move tables: z = 0..47, W cols at 1536 + z*128  [900,512] each
    tc_gemm_nt<<<dim3(NG / 128, (N_MV + 127) / 128, 48), 256>>>(
        move_emb, ED, N_MV, Wih, 7808, 1536, ED, p_tab_mv, NG, N_MV, ED, 0);

    // 6) fused gather + LSTM + MLP + masked softmax
    fused_tail_kernel<<<B, 512>>>(ability_ids, move_ids, c0, mask,
                                  bih, bhh, W1, b1, W2, b2, Wa, ba,
                                  (float*)d_out, B);
}

// round 7
// speedup vs baseline: 1.6465x; 1.1140x over previous
#include <cuda_runtime.h>
#include <math.h>
#include <stdint.h>

// Problem constants
#define ED 128
#define LH 128
#define HD 64
#define NG 512            // 4*LH
#define N_AB 300
#define N_MV 900
#define MAXB 4096

// -------- scratch (device globals; no allocations allowed) --------
__device__ float g_num[MAXB * ED];                  // numerical @ num_W^T + num_b   [B,128]
__device__ float g_gates[(size_t)MAXB * NG];        // gates partial (num + hh)      [B,512]
__device__ float g_tab_ab[12 * N_AB * NG];          // per-slot ability tables  (7.4 MB)
__device__ float g_tab_mv[48 * N_MV * NG];          // per-slot move tables     (88.5 MB)

__device__ __forceinline__ uint32_t f2tf32(float x) {
    uint32_t r;
    asm("cvt.rna.tf32.f32 %0, %1;" : "=r"(r) : "f"(x));
    return r;
}

// ---------------------------------------------------------------------------
// Tensor-core TF32 GEMM: C[z][r][c] (+)= sum_k A[r,k] * W[c, wColBase+z*step+k]
// CTA tile 128x128, BK=32, 256 threads (8 warps: 4 in M x 2 in N).
// ---------------------------------------------------------------------------
__global__ __launch_bounds__(256, 2)
void tc_gemm_nt(const float* __restrict__ A, int lda, int M,
                const float* __restrict__ W, int ldw, int wColBase, int wColStepZ,
                float* __restrict__ C, int ldc, int cRowsPerZ,
                int K, int accumulate)
{
    __shared__ __align__(16) float As[128][36];
    __shared__ __align__(16) float Bs[128][36];

    const int z = blockIdx.z;
    const float* Wz = W + (size_t)wColBase + (size_t)z * wColStepZ;
    float* Cz = C + (size_t)z * (size_t)cRowsPerZ * ldc;

    const int row0 = blockIdx.y * 128;
    const int col0 = blockIdx.x * 128;

    const int t    = threadIdx.x;
    const int lane = t & 31;
    const int wid  = t >> 5;
    const int wm   = wid & 3;          // 0..3 : 32-row band
    const int wn   = wid >> 2;         // 0..1 : 64-col band
    const int g    = lane >> 2;        // 0..7
    const int q    = lane & 3;         // 0..3

    const int lr = t >> 1;             // 0..127 load row
    const int lq = t & 1;              // float4 column parity

    float acc[2][8][4];
#pragma unroll
    for (int mi = 0; mi < 2; mi++)
#pragma unroll
        for (int ni = 0; ni < 8; ni++)
#pragma unroll
            for (int r = 0; r < 4; r++) acc[mi][ni][r] = 0.f;

    for (int k0 = 0; k0 < K; k0 += 32) {
        {
            const int gr = row0 + lr;
            const bool ok = (gr < M);
            const float* src = A + (size_t)gr * lda + k0;
#pragma unroll
            for (int it = 0; it < 4; it++) {
                const int f4 = lq + it * 2;       // 0..7
                float4 v = make_float4(0.f, 0.f, 0.f, 0.f);
                if (ok) v = *(const float4*)(src + f4 * 4);
                *(float4*)&As[lr][f4 * 4] = v;
            }
        }
        {
            const int gc = col0 + lr;
            const float* src = Wz + (size_t)gc * ldw + k0;
#pragma unroll
            for (int it = 0; it < 4; it++) {
                const int f4 = lq + it * 2;
                *(float4*)&Bs[lr][f4 * 4] = *(const float4*)(src + f4 * 4);
            }
        }
        __syncthreads();

#pragma unroll
        for (int kk = 0; kk < 4; kk++) {
            const int kb = kk * 8;
            uint32_t af[2][4];
#pragma unroll
            for (int mi = 0; mi < 2; mi++) {
                const int r = wm * 32 + mi * 16 + g;
                af[mi][0] = f2tf32(As[r][kb + q]);
                af[mi][1] = f2tf32(As[r + 8][kb + q]);
                af[mi][2] = f2tf32(As[r][kb + q + 4]);
                af[mi][3] = f2tf32(As[r + 8][kb + q + 4]);
            }
            uint32_t bf[8][2];
#pragma unroll
            for (int ni = 0; ni < 8; ni++) {
                const int c = wn * 64 + ni * 8 + g;
                bf[ni][0] = f2tf32(Bs[c][kb + q]);
                bf[ni][1] = f2tf32(Bs[c][kb + q + 4]);
            }
#pragma unroll
            for (int mi = 0; mi < 2; mi++)
#pragma unroll
                for (int ni = 0; ni < 8; ni++) {
                    asm volatile(
                        "mma.sync.aligned.m16n8k8.row.col.f32.tf32.tf32.f32 "
                        "{%0,%1,%2,%3}, {%4,%5,%6,%7}, {%8,%9}, {%0,%1,%2,%3};"
                        : "+f"(acc[mi][ni][0]), "+f"(acc[mi][ni][1]),
                          "+f"(acc[mi][ni][2]), "+f"(acc[mi][ni][3])
                        : "r"(af[mi][0]), "r"(af[mi][1]), "r"(af[mi][2]), "r"(af[mi][3]),
                          "r"(bf[ni][0]), "r"(bf[ni][1]));
                }
        }
        __syncthreads();
    }

#pragma unroll
    for (int mi = 0; mi < 2; mi++) {
        const int rA = row0 + wm * 32 + mi * 16 + g;
        const int rB = rA + 8;
#pragma unroll
        for (int ni = 0; ni < 8; ni++) {
            const int c = col0 + wn * 64 + ni * 8 + q * 2;
            if (rA < M) {
                float2* p = (float2*)(Cz + (size_t)rA * ldc + c);
                float2 v = make_float2(acc[mi][ni][0], acc[mi][ni][1]);
                if (accumulate) { float2 o = *p; v.x += o.x; v.y += o.y; }
                *p = v;
            }
            if (rB < M) {
                float2* p = (float2*)(Cz + (size_t)rB * ldc + c);
                float2 v = make_float2(acc[mi][ni][2], acc[mi][ni][3]);
                if (accumulate) { float2 o = *p; v.x += o.x; v.y += o.y; }
                *p = v;
            }
        }
    }
}

// ---------------------------------------------------------------------------
// Small GEMM for the num projection (K=84). 64x64x32 tiles, fp32 SIMT.
// ---------------------------------------------------------------------------
#define BM 64
#define BN 64
#define BK 32

__global__ void gemm_nt_kernel(const float* __restrict__ A, int lda,
                               const float* __restrict__ W, int ldw,
                               float* __restrict__ C, int ldc, int M,
                               int N, int K,
                               const float* __restrict__ bias)
{
    __shared__ float As[BK][BM + 1];
    __shared__ float Bs[BK][BN + 1];

    const int row0 = blockIdx.y * BM;
    const int col0 = blockIdx.x * BN;
    const int t  = threadIdx.x;
    const int tx = t & 15;
    const int ty = t >> 4;

    float acc[4][4];
#pragma unroll
    for (int i = 0; i < 4; i++)
#pragma unroll
        for (int j = 0; j < 4; j++) acc[i][j] = 0.f;

    const int lm = t >> 2;
    const int ks = (t & 3) * 8;

    for (int k0 = 0; k0 < K; k0 += BK) {
        {
            const int gr = row0 + lm;
            const bool rok = (gr < M);
            const size_t base = (size_t)gr * lda + k0 + ks;
#pragma unroll
            for (int i = 0; i < 8; i++) {
                const int k = k0 + ks + i;
                As[ks + i][lm] = (rok && k < K) ? A[base + i] : 0.f;
            }
        }
        {
            const int gc = col0 + lm;
            const bool cok = (gc < N);
            const size_t base = (size_t)gc * ldw + k0 + ks;
#pragma unroll
            for (int i = 0; i < 8; i++) {
                const int k = k0 + ks + i;
                Bs[ks + i][lm] = (cok && k < K) ? W[base + i] : 0.f;
            }
        }
        __syncthreads();

#pragma unroll
        for (int kk = 0; kk < BK; kk++) {
            float a[4], b[4];
#pragma unroll
            for (int i = 0; i < 4; i++) a[i] = As[kk][ty * 4 + i];
#pragma unroll
            for (int i = 0; i < 4; i++) b[i] = Bs[kk][tx * 4 + i];
#pragma unroll
            for (int i = 0; i < 4; i++)
#pragma unroll
                for (int j = 0; j < 4; j++)
                    acc[i][j] += a[i] * b[j];
        }
        __syncthreads();
    }

#pragma unroll
    for (int i = 0; i < 4; i++) {
        const int r = row0 + ty * 4 + i;
        if (r >= M) continue;
#pragma unroll
        for (int j = 0; j < 4; j++) {
            const int c = col0 + tx * 4 + j;
            if (c >= N) continue;
            float v = acc[i][j];
            if (bias) v += bias[c];
            C[(size_t)r * ldc + c] = v;
        }
    }
}

// ---------------------------------------------------------------------------
// Fused tail v2: one block of 128 threads per batch row; float4 gathers.
// Thread j owns gates 4j..4j+3 during accumulation (warp = 512B segment).
// Per-gate summation order identical to v1 (bitwise-same results).
// ---------------------------------------------------------------------------
__global__ __launch_bounds__(128, 8)
void fused_tail_v2(const int* __restrict__ ability_ids,
                   const int* __restrict__ move_ids,
                   const float* __restrict__ c0,
                   const float* __restrict__ mask,
                   const float* __restrict__ bih,
                   const float* __restrict__ bhh,
                   const float* __restrict__ W1,
                   const float* __restrict__ b1,
                   const float* __restrict__ W2,
                   const float* __restrict__ b2,
                   const float* __restrict__ Wa,
                   const float* __restrict__ ba,
                   float* __restrict__ out, int B)
{
    __shared__ int   s_aid[12];
    __shared__ int   s_mid[48];
    __shared__ __align__(16) float s_g[NG];
    __shared__ float s_h1[LH];
    __shared__ float s_t1[HD];
    __shared__ float s_feat[ED];
    __shared__ float s_logits[9];

    const int b = blockIdx.x;
    const int j = threadIdx.x;          // 0..127

    if (j < 12)      s_aid[j]      = ability_ids[b * 12 + j];
    else if (j < 60) s_mid[j - 12] = move_ids[b * 48 + (j - 12)];
    __syncthreads();

    // ---- gate accumulation: float4 per thread, same per-gate sum order as v1
    {
        const size_t c4 = (size_t)4 * j;
        float4 acc = *(const float4*)(g_gates + (size_t)b * NG + c4);
        const float4 bi = *(const float4*)(bih + c4);
        const float4 bh = *(const float4*)(bhh + c4);
        acc.x += bi.x + bh.x; acc.y += bi.y + bh.y;
        acc.z += bi.z + bh.z; acc.w += bi.w + bh.w;
#pragma unroll
        for (int s = 0; s < 12; s++) {
            const float4 v = *(const float4*)(
                g_tab_ab + ((size_t)(s * N_AB + s_aid[s])) * NG + c4);
            acc.x += v.x; acc.y += v.y; acc.z += v.z; acc.w += v.w;
        }
#pragma unroll
        for (int s = 0; s < 48; s++) {
            const float4 v = *(const float4*)(
                g_tab_mv + ((size_t)(s * N_MV + s_mid[s])) * NG + c4);
            acc.x += v.x; acc.y += v.y; acc.z += v.z; acc.w += v.w;
        }
        *(float4*)(s_g + c4) = acc;
    }
    __syncthreads();

    // ---- LSTM cell (torch gate order i,f,g,o); thread j = hidden unit j
    {
        const float iv = 1.f / (1.f + expf(-s_g[j]));
        const float fv = 1.f / (1.f + expf(-s_g[LH + j]));
        const float gv = tanhf(s_g[2 * LH + j]);
        const float ov = 1.f / (1.f + expf(-s_g[3 * LH + j]));
        const float c1 = fv * c0[(size_t)b * LH + j] + iv * gv;
        const float h1 = ov * tanhf(c1);
        s_h1[j] = h1;
        out[(size_t)B * 9 + (size_t)b * LH + j] = h1;
        out[(size_t)B * 9 + (size_t)B * LH + (size_t)b * LH + j] = c1;
    }
    __syncthreads();

    // ---- MLP: t1 = relu(h1 @ W1^T + b1)   (threads 0..63)
    if (j < HD) {
        float a = b1[j];
#pragma unroll
        for (int t = 0; t < LH; t++) a += W1[j * LH + t] * s_h1[t];
        s_t1[j] = fmaxf(a, 0.f);
    }
    __syncthreads();

    // ---- feat = t1 @ W2^T + b2   (all 128 threads)
    {
        float a = b2[j];
#pragma unroll
        for (int t = 0; t < HD; t++) a += W2[j * HD + t] * s_t1[t];
        s_feat[j] = a;
    }
    __syncthreads();

    // ---- logits = feat @ Wa^T + ba   (threads 0..8)
    if (j < 9) {
        float a = ba[j];
#pragma unroll
        for (int t = 0; t < ED; t++) a += Wa[j * ED + t] * s_feat[t];
        s_logits[j] = a;
    }
    __syncthreads();

    // ---- softmax + masked renormalization
    if (j == 0) {
        float mx = s_logits[0];
#pragma unroll
        for (int a = 1; a < 9; a++) mx = fmaxf(mx, s_logits[a]);
        float p[9], sum = 0.f;
#pragma unroll
        for (int a = 0; a < 9; a++) { p[a] = expf(s_logits[a] - mx); sum += p[a]; }
        float pm[9], msum = 0.f;
#pragma unroll
        for (int a = 0; a < 9; a++) {
            p[a] /= sum;
            pm[a] = p[a] * mask[(size_t)b * 9 + a];
            msum += pm[a];
        }
#pragma unroll
        for (int a = 0; a < 9; a++)
            out[(size_t)b * 9 + a] = (msum > 0.f) ? (pm[a] / msum) : p[a];
    }
}

// ---------------------------------------------------------------------------
extern "C" void kernel_launch(void* const* d_in, const int* in_sizes, int n_in,
                              void* d_out, int out_size)
{
    const int*   ability_ids = (const int*)  d_in[0];
    const int*   move_ids    = (const int*)  d_in[1];
    const float* numerical   = (const float*)d_in[2];
    const float* mask        = (const float*)d_in[3];
    const float* h0          = (const float*)d_in[4];
    const float* c0          = (const float*)d_in[5];
    const float* ability_emb = (const float*)d_in[6];
    const float* move_emb    = (const float*)d_in[7];
    const float* num_W       = (const float*)d_in[8];
    const float* num_b       = (const float*)d_in[9];
    const float* Wih         = (const float*)d_in[10];
    const float* Whh         = (const float*)d_in[11];
    const float* bih         = (const float*)d_in[12];
    const float* bhh         = (const float*)d_in[13];
    const float* W1          = (const float*)d_in[14];
    const float* b1          = (const float*)d_in[15];
    const float* W2          = (const float*)d_in[16];
    const float* b2          = (const float*)d_in[17];
    const float* Wa          = (const float*)d_in[18];
    const float* ba          = (const float*)d_in[19];

    const int B = in_sizes[0] / 12;   // 4096

    float *p_num, *p_gates, *p_tab_ab, *p_tab_mv;
    cudaGetSymbolAddress((void**)&p_num,    g_num);
    cudaGetSymbolAddress((void**)&p_gates,  g_gates);
    cudaGetSymbolAddress((void**)&p_tab_ab, g_tab_ab);
    cudaGetSymbolAddress((void**)&p_tab_mv, g_tab_mv);

    // 1) num = numerical @ num_W^T + num_b      [B,128], K=84 (SIMT)
    gemm_nt_kernel<<<dim3(2, (B + BM - 1) / BM, 1), 256>>>(
        numerical, 84, num_W, 84, p_num, ED, B, ED, 84, num_b);

    // 2) gates = num @ Wih[:,7680:7808]^T       [B,512], K=128 (TF32 TC)
    tc_gemm_nt<<<dim3(NG / 128, B / 128, 1), 256>>>(
        p_num, ED, B, Wih, 7808, 7680, 0, p_gates, NG, B, ED, 0);

    // 3) gates += h0 @ Whh^T                    [B,512], K=128
    tc_gemm_nt<<<dim3(NG / 128, B / 128, 1), 256>>>(
        h0, LH, B, Whh, LH, 0, 0, p_gates, NG, B, LH, 1);

    // 4) ability tables: z = 0..11, W cols at z*128      [300,512] each
    tc_gemm_nt<<<dim3(NG / 128, (N_AB + 127) / 128, 12), 256>>>(
        ability_emb, ED, N_AB, Wih, 7808, 0, ED, p_tab_ab, NG, N_AB, ED, 0);

    // 5) move tables: z = 0..47, W cols at 1536 + z*128  [900,512] each
    tc_gemm_nt<<<dim3(NG / 128, (N_MV + 127) / 128, 48), 256>>>(
        move_emb, ED, N_MV, Wih, 7808, 1536, ED, p_tab_mv, NG, N_MV, ED, 0);

    // 6) fused gather + LSTM + MLP + masked softmax (float4 tail)
    fused_tail_v2<<<B, 128>>>(ability_ids, move_ids, c0, mask,
                              bih, bhh, W1, b1, W2, b2, Wa, ba,
                              (float*)d_out, B);
}

// round 8
// speedup vs baseline: 1.6922x; 1.0277x over previous
#include <cuda_runtime.h>
#include <math.h>
#include <stdint.h>

// Problem constants
#define ED 128
#define LH 128
#define HD 64
#define NG 512            // 4*LH
#define N_AB 300
#define N_MV 900
#define MAXB 4096
#define IN_DIM 7808

// -------- scratch (device globals; no allocations allowed) --------
__device__ float g_num[MAXB * ED];                  // tf32-rounded num projection [B,128]
__device__ float g_gates[(size_t)MAXB * NG];        // gates partial (num + hh)    [B,512]
__device__ float g_tab_ab[12 * N_AB * NG];          // per-slot ability tables  (7.4 MB)
__device__ float g_tab_mv[48 * N_MV * NG];          // per-slot move tables     (88.5 MB)
// tf32-rounded copies of GEMM operands
__device__ float g_Wih_t[(size_t)NG * IN_DIM];      // 16 MB
__device__ float g_Whh_t[NG * LH];
__device__ float g_abemb_t[N_AB * ED];
__device__ float g_mvemb_t[N_MV * ED];
__device__ float g_h0_t[MAXB * LH];

__device__ __forceinline__ uint32_t f2tf32(float x) {
    uint32_t r;
    asm("cvt.rna.tf32.f32 %0, %1;" : "=r"(r) : "f"(x));
    return r;
}

__device__ __forceinline__ void cp_async16(void* smem, const void* gmem, bool valid) {
    uint32_t s = (uint32_t)__cvta_generic_to_shared(smem);
    int sz = valid ? 16 : 0;
    asm volatile("cp.async.cg.shared.global [%0], [%1], 16, %2;"
                 :: "r"(s), "l"(gmem), "r"(sz));
}

// ---------------------------------------------------------------------------
// Elementwise tf32-rounding pass (float4). n4 = n/4.
// ---------------------------------------------------------------------------
__global__ void cvt_tf32_kernel(const float* __restrict__ src,
                                float* __restrict__ dst, int n4)
{
    int i = blockIdx.x * blockDim.x + threadIdx.x;
    if (i < n4) {
        float4 v = ((const float4*)src)[i];
        v.x = __uint_as_float(f2tf32(v.x));
        v.y = __uint_as_float(f2tf32(v.y));
        v.z = __uint_as_float(f2tf32(v.z));
        v.w = __uint_as_float(f2tf32(v.w));
        ((float4*)dst)[i] = v;
    }
}

// ---------------------------------------------------------------------------
// Tensor-core TF32 GEMM (inputs pre-rounded to tf32 bit patterns):
// C[z][r][c] (+)= sum_k A[r,k] * W[c, wColBase+z*step+k]
// CTA 128x128, BK=32, 256 threads, cp.async double-buffered, pure LDS+MMA core.
// Requirements: grid.x*128 == N exactly, K % 32 == 0, 16B-aligned rows.
// ---------------------------------------------------------------------------
__global__ __launch_bounds__(256, 2)
void tc_gemm_nt(const float* __restrict__ A, int lda, int M,
                const float* __restrict__ W, int ldw, int wColBase, int wColStepZ,
                float* __restrict__ C, int ldc, int cRowsPerZ,
                int K, int accumulate)
{
    __shared__ __align__(16) float As[2][128][36];
    __shared__ __align__(16) float Bs[2][128][36];

    const int z = blockIdx.z;
    const float* Wz = W + (size_t)wColBase + (size_t)z * wColStepZ;
    float* Cz = C + (size_t)z * (size_t)cRowsPerZ * ldc;

    const int row0 = blockIdx.y * 128;
    const int col0 = blockIdx.x * 128;

    const int t    = threadIdx.x;
    const int lane = t & 31;
    const int wid  = t >> 5;
    const int wm   = wid & 3;          // 0..3 : 32-row band
    const int wn   = wid >> 2;         // 0..1 : 64-col band
    const int g    = lane >> 2;        // 0..7
    const int q    = lane & 3;         // 0..3

    const int lr = t >> 1;             // 0..127 load row
    const int lq = t & 1;              // float4 column parity

    const int  gr  = row0 + lr;
    const bool okA = (gr < M);
    const float* srcA = A + (size_t)(okA ? gr : 0) * lda;
    const float* srcW = Wz + (size_t)(col0 + lr) * ldw;

    float acc[2][8][4];
#pragma unroll
    for (int mi = 0; mi < 2; mi++)
#pragma unroll
        for (int ni = 0; ni < 8; ni++)
#pragma unroll
            for (int r = 0; r < 4; r++) acc[mi][ni][r] = 0.f;

    const int tiles = K >> 5;

    // issue tile 0
    {
#pragma unroll
        for (int it = 0; it < 4; it++) {
            const int f4 = lq + it * 2;
            cp_async16(&As[0][lr][f4 * 4], srcA + f4 * 4, okA);
            cp_async16(&Bs[0][lr][f4 * 4], srcW + f4 * 4, true);
        }
        asm volatile("cp.async.commit_group;");
    }

    for (int tt = 0; tt < tiles; tt++) {
        const int buf = tt & 1;
        if (tt + 1 < tiles) {
            const int nb = (tt + 1) & 1;
            const int k0 = (tt + 1) * 32;
#pragma unroll
            for (int it = 0; it < 4; it++) {
                const int f4 = lq + it * 2;
                cp_async16(&As[nb][lr][f4 * 4], srcA + k0 + f4 * 4, okA);
                cp_async16(&Bs[nb][lr][f4 * 4], srcW + k0 + f4 * 4, true);
            }
            asm volatile("cp.async.commit_group;");
            asm volatile("cp.async.wait_group 1;");
        } else {
            asm volatile("cp.async.wait_group 0;");
        }
        __syncthreads();

#pragma unroll
        for (int kk = 0; kk < 4; kk++) {
            const int kb = kk * 8;
            uint32_t af[2][4];
#pragma unroll
            for (int mi = 0; mi < 2; mi++) {
                const int r = wm * 32 + mi * 16 + g;
                af[mi][0] = __float_as_uint(As[buf][r][kb + q]);
                af[mi][1] = __float_as_uint(As[buf][r + 8][kb + q]);
                af[mi][2] = __float_as_uint(As[buf][r][kb + q + 4]);
                af[mi][3] = __float_as_uint(As[buf][r + 8][kb + q + 4]);
            }
            uint32_t bf[8][2];
#pragma unroll
            for (int ni = 0; ni < 8; ni++) {
                const int c = wn * 64 + ni * 8 + g;
                bf[ni][0] = __float_as_uint(Bs[buf][c][kb + q]);
                bf[ni][1] = __float_as_uint(Bs[buf][c][kb + q + 4]);
            }
#pragma unroll
            for (int mi = 0; mi < 2; mi++)
#pragma unroll
                for (int ni = 0; ni < 8; ni++) {
                    asm volatile(
                        "mma.sync.aligned.m16n8k8.row.col.f32.tf32.tf32.f32 "
                        "{%0,%1,%2,%3}, {%4,%5,%6,%7}, {%8,%9}, {%0,%1,%2,%3};"
                        : "+f"(acc[mi][ni][0]), "+f"(acc[mi][ni][1]),
                          "+f"(acc[mi][ni][2]), "+f"(acc[mi][ni][3])
                        : "r"(af[mi][0]), "r"(af[mi][1]), "r"(af[mi][2]), "r"(af[mi][3]),
                          "r"(bf[ni][0]), "r"(bf[ni][1]));
                }
        }
        __syncthreads();
    }

#pragma unroll
    for (int mi = 0; mi < 2; mi++) {
        const int rA = row0 + wm * 32 + mi * 16 + g;
        const int rB = rA + 8;
#pragma unroll
        for (int ni = 0; ni < 8; ni++) {
            const int c = col0 + wn * 64 + ni * 8 + q * 2;
            if (rA < M) {
                float2* p = (float2*)(Cz + (size_t)rA * ldc + c);
                float2 v = make_float2(acc[mi][ni][0], acc[mi][ni][1]);
                if (accumulate) { float2 o = *p; v.x += o.x; v.y += o.y; }
                *p = v;
            }
            if (rB < M) {
                float2* p = (float2*)(Cz + (size_t)rB * ldc + c);
                float2 v = make_float2(acc[mi][ni][2], acc[mi][ni][3]);
                if (accumulate) { float2 o = *p; v.x += o.x; v.y += o.y; }
                *p = v;
            }
        }
    }
}

// ---------------------------------------------------------------------------
// Small GEMM for the num projection (K=84), fp32 SIMT; output tf32-rounded
// (it feeds the gates tensor-core GEMM as A).
// ---------------------------------------------------------------------------
#define BM 64
#define BN 64
#define BK 32

__global__ void gemm_nt_kernel(const float* __restrict__ A, int lda,
                               const float* __restrict__ W, int ldw,
                               float* __restrict__ C, int ldc, int M,
                               int N, int K,
                               const float* __restrict__ bias)
{
    __shared__ float As[BK][BM + 1];
    __shared__ float Bs[BK][BN + 1];

    const int row0 = blockIdx.y * BM;
    const int col0 = blockIdx.x * BN;
    const int t  = threadIdx.x;
    const int tx = t & 15;
    const int ty = t >> 4;

    float acc[4][4];
#pragma unroll
    for (int i = 0; i < 4; i++)
#pragma unroll
        for (int j = 0; j < 4; j++) acc[i][j] = 0.f;

    const int lm = t >> 2;
    const int ks = (t & 3) * 8;

    for (int k0 = 0; k0 < K; k0 += BK) {
        {
            const int gr = row0 + lm;
            const bool rok = (gr < M);
            const size_t base = (size_t)gr * lda + k0 + ks;
#pragma unroll
            for (int i = 0; i < 8; i++) {
                const int k = k0 + ks + i;
                As[ks + i][lm] = (rok && k < K) ? A[base + i] : 0.f;
            }
        }
        {
            const int gc = col0 + lm;
            const bool cok = (gc < N);
            const size_t base = (size_t)gc * ldw + k0 + ks;
#pragma unroll
            for (int i = 0; i < 8; i++) {
                const int k = k0 + ks + i;
                Bs[ks + i][lm] = (cok && k < K) ? W[base + i] : 0.f;
            }
        }
        __syncthreads();

#pragma unroll
        for (int kk = 0; kk < BK; kk++) {
            float a[4], b[4];
#pragma unroll
            for (int i = 0; i < 4; i++) a[i] = As[kk][ty * 4 + i];
#pragma unroll
            for (int i = 0; i < 4; i++) b[i] = Bs[kk][tx * 4 + i];
#pragma unroll
            for (int i = 0; i < 4; i++)
#pragma unroll
                for (int j = 0; j < 4; j++)
                    acc[i][j] += a[i] * b[j];
        }
        __syncthreads();
    }

#pragma unroll
    for (int i = 0; i < 4; i++) {
        const int r = row0 + ty * 4 + i;
        if (r >= M) continue;
#pragma unroll
        for (int j = 0; j < 4; j++) {
            const int c = col0 + tx * 4 + j;
            if (c >= N) continue;
            float v = acc[i][j];
            if (bias) v += bias[c];
            C[(size_t)r * ldc + c] = __uint_as_float(f2tf32(v));
        }
    }
}

// ---------------------------------------------------------------------------
// Fused tail v2: one 128-thread block per batch row; float4 gathers.
// ---------------------------------------------------------------------------
__global__ __launch_bounds__(128, 8)
void fused_tail_v2(const int* __restrict__ ability_ids,
                   const int* __restrict__ move_ids,
                   const float* __restrict__ c0,
                   const float* __restrict__ mask,
                   const float* __restrict__ bih,
                   const float* __restrict__ bhh,
                   const float* __restrict__ W1,
                   const float* __restrict__ b1,
                   const float* __restrict__ W2,
                   const float* __restrict__ b2,
                   const float* __restrict__ Wa,
                   const float* __restrict__ ba,
                   float* __restrict__ out, int B)
{
    __shared__ int   s_aid[12];
    __shared__ int   s_mid[48];
    __shared__ __align__(16) float s_g[NG];
    __shared__ float s_h1[LH];
    __shared__ float s_t1[HD];
    __shared__ float s_feat[ED];
    __shared__ float s_logits[9];

    const int b = blockIdx.x;
    const int j = threadIdx.x;          // 0..127

    if (j < 12)      s_aid[j]      = ability_ids[b * 12 + j];
    else if (j < 60) s_mid[j - 12] = move_ids[b * 48 + (j - 12)];
    __syncthreads();

    {
        const size_t c4 = (size_t)4 * j;
        float4 acc = *(const float4*)(g_gates + (size_t)b * NG + c4);
        const float4 bi = *(const float4*)(bih + c4);
        const float4 bh = *(const float4*)(bhh + c4);
        acc.x += bi.x + bh.x; acc.y += bi.y + bh.y;
        acc.z += bi.z + bh.z; acc.w += bi.w + bh.w;
#pragma unroll
        for (int s = 0; s < 12; s++) {
            const float4 v = *(const float4*)(
                g_tab_ab + ((size_t)(s * N_AB + s_aid[s])) * NG + c4);
            acc.x += v.x; acc.y += v.y; acc.z += v.z; acc.w += v.w;
        }
#pragma unroll
        for (int s = 0; s < 48; s++) {
            const float4 v = *(const float4*)(
                g_tab_mv + ((size_t)(s * N_MV + s_mid[s])) * NG + c4);
            acc.x += v.x; acc.y += v.y; acc.z += v.z; acc.w += v.w;
        }
        *(float4*)(s_g + c4) = acc;
    }
    __syncthreads();

    {
        const float iv = 1.f / (1.f + expf(-s_g[j]));
        const float fv = 1.f / (1.f + expf(-s_g[LH + j]));
        const float gv = tanhf(s_g[2 * LH + j]);
        const float ov = 1.f / (1.f + expf(-s_g[3 * LH + j]));
        const float c1 = fv * c0[(size_t)b * LH + j] + iv * gv;
        const float h1 = ov * tanhf(c1);
        s_h1[j] = h1;
        out[(size_t)B * 9 + (size_t)b * LH + j] = h1;
        out[(size_t)B * 9 + (size_t)B * LH + (size_t)b * LH + j] = c1;
    }
    __syncthreads();

    if (j < HD) {
        float a = b1[j];
#pragma unroll
        for (int t = 0; t < LH; t++) a += W1[j * LH + t] * s_h1[t];
        s_t1[j] = fmaxf(a, 0.f);
    }
    __syncthreads();

    {
        float a = b2[j];
#pragma unroll
        for (int t = 0; t < HD; t++) a += W2[j * HD + t] * s_t1[t];
        s_feat[j] = a;
    }
    __syncthreads();

    if (j < 9) {
        float a = ba[j];
#pragma unroll
        for (int t = 0; t < ED; t++) a += Wa[j * ED + t] * s_feat[t];
        s_logits[j] = a;
    }
    __syncthreads();

    if (j == 0) {
        float mx = s_logits[0];
#pragma unroll
        for (int a = 1; a < 9; a++) mx = fmaxf(mx, s_logits[a]);
        float p[9], sum = 0.f;
#pragma unroll
        for (int a = 0; a < 9; a++) { p[a] = expf(s_logits[a] - mx); sum += p[a]; }
        float pm[9], msum = 0.f;
#pragma unroll
        for (int a = 0; a < 9; a++) {
            p[a] /= sum;
            pm[a] = p[a] * mask[(size_t)b * 9 + a];
            msum += pm[a];
        }
#pragma unroll
        for (int a = 0; a < 9; a++)
            out[(size_t)b * 9 + a] = (msum > 0.f) ? (pm[a] / msum) : p[a];
    }
}

// ---------------------------------------------------------------------------
extern "C" void kernel_launch(void* const* d_in, const int* in_sizes, int n_in,
                              void* d_out, int out_size)
{
    const int*   ability_ids = (const int*)  d_in[0];
    const int*   move_ids    = (const int*)  d_in[1];
    const float* numerical   = (const float*)d_in[2];
    const float* mask        = (const float*)d_in[3];
    const float* h0          = (const float*)d_in[4];
    const float* c0          = (const float*)d_in[5];
    const float* ability_emb = (const float*)d_in[6];
    const float* move_emb    = (const float*)d_in[7];
    const float* num_W       = (const float*)d_in[8];
    const float* num_b       = (const float*)d_in[9];
    const float* Wih         = (const float*)d_in[10];
    const float* Whh         = (const float*)d_in[11];
    const float* bih         = (const float*)d_in[12];
    const float* bhh         = (const float*)d_in[13];
    const float* W1          = (const float*)d_in[14];
    const float* b1          = (const float*)d_in[15];
    const float* W2          = (const float*)d_in[16];
    const float* b2          = (const float*)d_in[17];
    const float* Wa          = (const float*)d_in[18];
    const float* ba          = (const float*)d_in[19];

    const int B = in_sizes[0] / 12;   // 4096

    float *p_num, *p_gates, *p_tab_ab, *p_tab_mv;
    float *p_Wih, *p_Whh, *p_ab, *p_mv, *p_h0;
    cudaGetSymbolAddress((void**)&p_num,    g_num);
    cudaGetSymbolAddress((void**)&p_gates,  g_gates);
    cudaGetSymbolAddress((void**)&p_tab_ab, g_tab_ab);
    cudaGetSymbolAddress((void**)&p_tab_mv, g_tab_mv);
    cudaGetSymbolAddress((void**)&p_Wih,    g_Wih_t);
    cudaGetSymbolAddress((void**)&p_Whh,    g_Whh_t);
    cudaGetSymbolAddress((void**)&p_ab,     g_abemb_t);
    cudaGetSymbolAddress((void**)&p_mv,     g_mvemb_t);
    cudaGetSymbolAddress((void**)&p_h0,     g_h0_t);

    // 0) tf32-round all tensor-core GEMM operands
    {
        int n4;
        n4 = NG * IN_DIM / 4;
        cvt_tf32_kernel<<<(n4 + 255) / 256, 256>>>(Wih, p_Wih, n4);
        n4 = NG * LH / 4;
        cvt_tf32_kernel<<<(n4 + 255) / 256, 256>>>(Whh, p_Whh, n4);
        n4 = N_AB * ED / 4;
        cvt_tf32_kernel<<<(n4 + 255) / 256, 256>>>(ability_emb, p_ab, n4);
        n4 = N_MV * ED / 4;
        cvt_tf32_kernel<<<(n4 + 255) / 256, 256>>>(move_emb, p_mv, n4);
        n4 = B * LH / 4;
        cvt_tf32_kernel<<<(n4 + 255) / 256, 256>>>(h0, p_h0, n4);
    }

    // 1) num = tf32(numerical @ num_W^T + num_b)   [B,128], K=84 (SIMT)
    gemm_nt_kernel<<<dim3(2, (B + BM - 1) / BM, 1), 256>>>(
        numerical, 84, num_W, 84, p_num, ED, B, ED, 84, num_b);

    // 2) gates = num @ Wih[:,7680:7808]^T          [B,512], K=128 (TF32 TC)
    tc_gemm_nt<<<dim3(NG / 128, B / 128, 1), 256>>>(
        p_num, ED, B, p_Wih, IN_DIM, 7680, 0, p_gates, NG, B, ED, 0);

    // 3) gates += h0 @ Whh^T                       [B,512], K=128
    tc_gemm_nt<<<dim3(NG / 128, B / 128, 1), 256>>>(
        p_h0, LH, B, p_Whh, LH, 0, 0, p_gates, NG, B, LH, 1);

    // 4) ability tables: z = 0..11, W cols at z*128
    tc_gemm_nt<<<dim3(NG / 128, (N_AB + 127) / 128, 12), 256>>>(
        p_ab, ED, N_AB, p_Wih, IN_DIM, 0, ED, p_tab_ab, NG, N_AB, ED, 0);

    // 5) move tables: z = 0..47, W cols at 1536 + z*128
    tc_gemm_nt<<<dim3(NG / 128, (N_MV + 127) / 128, 48), 256>>>(
        p_mv, ED, N_MV, p_Wih, IN_DIM, 1536, ED, p_tab_mv, NG, N_MV, ED, 0);

    // 6) fused gather + LSTM + MLP + masked softmax
    fused_tail_v2<<<B, 128>>>(ability_ids, move_ids, c0, mask,
                              bih, bhh, W1, b1, W2, b2, Wa, ba,
                              (float*)d_out, B);
}

// round 10
// speedup vs baseline: 1.7278x; 1.0211x over previous
#include <cuda_runtime.h>
#include <math.h>
#include <stdint.h>

// Problem constants
#define ED 128
#define LH 128
#define HD 64
#define NG 512            // 4*LH
#define N_AB 300
#define N_MV 900
#define MAXB 4096
#define IN_DIM 7808

// -------- scratch (device globals; no allocations allowed) --------
__device__ float g_num[MAXB * ED];                  // tf32+perm num projection [B,128]
__device__ float g_gates[(size_t)MAXB * NG];        // gates partial (num + hh) [B,512]
__device__ float g_tab_ab[12 * N_AB * NG];          // per-slot ability tables
__device__ float g_tab_mv[48 * N_MV * NG];          // per-slot move tables
// tf32-rounded + column-permuted copies of GEMM operands
__device__ float g_Wih_t[(size_t)NG * IN_DIM];
__device__ float g_Whh_t[NG * LH];
__device__ float g_abemb_t[N_AB * ED];
__device__ float g_mvemb_t[N_MV * ED];
__device__ float g_h0_t[MAXB * LH];

__device__ __forceinline__ uint32_t f2tf32(float x) {
    uint32_t r;
    asm("cvt.rna.tf32.f32 %0, %1;" : "=r"(r) : "f"(x));
    return r;
}

__device__ __forceinline__ void cp_async16(void* smem, const void* gmem, bool valid) {
    uint32_t s = (uint32_t)__cvta_generic_to_shared(smem);
    int sz = valid ? 16 : 0;
    asm volatile("cp.async.cg.shared.global [%0], [%1], 16, %2;"
                 :: "r"(s), "l"(gmem), "r"(sz));
}

// column permutation within each 32-col group: c -> (c&3)*8 + (c>>2)
__device__ __forceinline__ int perm32(int c) {
    return (c & ~31) | (((c & 3) << 3) | ((c & 31) >> 2));
}

// ---------------------------------------------------------------------------
// Fused tf32-round + permute pass over 5 buffers (float4-indexed lengths).
// ---------------------------------------------------------------------------
__global__ void cvt_perm5(const float4* __restrict__ s0, float* __restrict__ d0, int n0,
                          const float4* __restrict__ s1, float* __restrict__ d1, int n1,
                          const float4* __restrict__ s2, float* __restrict__ d2, int n2,
                          const float4* __restrict__ s3, float* __restrict__ d3, int n3,
                          const float4* __restrict__ s4, float* __restrict__ d4, int n4)
{
    int i = blockIdx.x * blockDim.x + threadIdx.x;
    const float4* s; float* d; int local = i;
    if      (local <  n0) { s = s0; d = d0; }
    else if ((local -= n0) < n1) { s = s1; d = d1; }
    else if ((local -= n1) < n2) { s = s2; d = d2; }
    else if ((local -= n2) < n3) { s = s3; d = d3; }
    else if ((local -= n3) < n4) { s = s4; d = d4; }
    else return;

    float4 v = s[local];
    const int base = (local * 4) & ~31;   // 32-col group base
    const int m = local & 7;              // c>>2 within group
    d[base +  0 + m] = __uint_as_float(f2tf32(v.x));
    d[base +  8 + m] = __uint_as_float(f2tf32(v.y));
    d[base + 16 + m] = __uint_as_float(f2tf32(v.z));
    d[base + 24 + m] = __uint_as_float(f2tf32(v.w));
}

// ---------------------------------------------------------------------------
// Tensor-core mainloop over permuted operands. CTA 128x128, BK=32,
// 256 threads (8 warps: 4 in M x 2 in N), double-buffered cp.async.
// Fragment loads are 2x LDS.128 per row thanks to the column permutation.
// ---------------------------------------------------------------------------
__device__ __forceinline__ void tc_mainloop(
    const float* __restrict__ srcA, bool okA,     // = A + rowA*lda (row clamped if !okA)
    const float* __restrict__ srcW,               // = W + (col0+lr)*ldw
    int tiles,
    float (*As)[128][36], float (*Bs)[128][36],
    float (&acc)[2][8][4])
{
    const int t    = threadIdx.x;
    const int lane = t & 31;
    const int wid  = t >> 5;
    const int wm   = wid & 3;
    const int wn   = wid >> 2;
    const int g    = lane >> 2;
    const int q    = lane & 3;
    const int lr   = t >> 1;
    const int lq   = t & 1;

#pragma unroll
    for (int it = 0; it < 4; it++) {
        const int f4 = lq + it * 2;
        cp_async16(&As[0][lr][f4 * 4], srcA + f4 * 4, okA);
        cp_async16(&Bs[0][lr][f4 * 4], srcW + f4 * 4, true);
    }
    asm volatile("cp.async.commit_group;");

    for (int tt = 0; tt < tiles; tt++) {
        const int buf = tt & 1;
        if (tt + 1 < tiles) {
            const int nb = (tt + 1) & 1;
            const int k0 = (tt + 1) * 32;
#pragma unroll
            for (int it = 0; it < 4; it++) {
                const int f4 = lq + it * 2;
                cp_async16(&As[nb][lr][f4 * 4], srcA + k0 + f4 * 4, okA);
                cp_async16(&Bs[nb][lr][f4 * 4], srcW + k0 + f4 * 4, true);
            }
            asm volatile("cp.async.commit_group;");
            asm volatile("cp.async.wait_group 1;");
        } else {
            asm volatile("cp.async.wait_group 0;");
        }
        __syncthreads();

        // A fragments for the whole 32-k tile: 8 LDS.128
        float aG[2][8], aG8[2][8];
#pragma unroll
        for (int mi = 0; mi < 2; mi++) {
            const int r0 = wm * 32 + mi * 16 + g;
            const float4 x0 = *(const float4*)&As[buf][r0][q * 8];
            const float4 x1 = *(const float4*)&As[buf][r0][q * 8 + 4];
            const float4 y0 = *(const float4*)&As[buf][r0 + 8][q * 8];
            const float4 y1 = *(const float4*)&As[buf][r0 + 8][q * 8 + 4];
            aG[mi][0] = x0.x; aG[mi][1] = x0.y; aG[mi][2] = x0.z; aG[mi][3] = x0.w;
            aG[mi][4] = x1.x; aG[mi][5] = x1.y; aG[mi][6] = x1.z; aG[mi][7] = x1.w;
            aG8[mi][0] = y0.x; aG8[mi][1] = y0.y; aG8[mi][2] = y0.z; aG8[mi][3] = y0.w;
            aG8[mi][4] = y1.x; aG8[mi][5] = y1.y; aG8[mi][6] = y1.z; aG8[mi][7] = y1.w;
        }

#pragma unroll
        for (int ni = 0; ni < 8; ni++) {
            const int c = wn * 64 + ni * 8 + g;
            const float4 b0 = *(const float4*)&Bs[buf][c][q * 8];
            const float4 b1 = *(const float4*)&Bs[buf][c][q * 8 + 4];
            float bb[8] = {b0.x, b0.y, b0.z, b0.w, b1.x, b1.y, b1.z, b1.w};
#pragma unroll
            for (int kk = 0; kk < 4; kk++) {
#pragma unroll
                for (int mi = 0; mi < 2; mi++) {
                    asm volatile(
                        "mma.sync.aligned.m16n8k8.row.col.f32.tf32.tf32.f32 "
                        "{%0,%1,%2,%3}, {%4,%5,%6,%7}, {%8,%9}, {%0,%1,%2,%3};"
                        : "+f"(acc[mi][ni][0]), "+f"(acc[mi][ni][1]),
                          "+f"(acc[mi][ni][2]), "+f"(acc[mi][ni][3])
                        : "r"(__float_as_uint(aG[mi][2 * kk])),
                          "r"(__float_as_uint(aG8[mi][2 * kk])),
                          "r"(__float_as_uint(aG[mi][2 * kk + 1])),
                          "r"(__float_as_uint(aG8[mi][2 * kk + 1])),
                          "r"(__float_as_uint(bb[2 * kk])),
                          "r"(__float_as_uint(bb[2 * kk + 1])));
                }
            }
        }
        __syncthreads();
    }
}

__device__ __forceinline__ void tc_epilogue(float (&acc)[2][8][4],
                                            float* __restrict__ Cz, int ldc,
                                            int row0, int col0, int M)
{
    const int t    = threadIdx.x;
    const int lane = t & 31;
    const int wid  = t >> 5;
    const int wm   = wid & 3;
    const int wn   = wid >> 2;
    const int g    = lane >> 2;
    const int q    = lane & 3;

#pragma unroll
    for (int mi = 0; mi < 2; mi++) {
        const int rA = row0 + wm * 32 + mi * 16 + g;
        const int rB = rA + 8;
#pragma unroll
        for (int ni = 0; ni < 8; ni++) {
            const int c = col0 + wn * 64 + ni * 8 + q * 2;
            if (rA < M)
                *(float2*)(Cz + (size_t)rA * ldc + c) =
                    make_float2(acc[mi][ni][0], acc[mi][ni][1]);
            if (rB < M)
                *(float2*)(Cz + (size_t)rB * ldc + c) =
                    make_float2(acc[mi][ni][2], acc[mi][ni][3]);
        }
    }
}

// ---------------------------------------------------------------------------
// Gates GEMM: gates = num @ WihT[:,7680:]^T + h0 @ Whh^T  (one kernel)
// ---------------------------------------------------------------------------
__global__ __launch_bounds__(256, 2)
void tc_gemm_gates(const float* __restrict__ numP,
                   const float* __restrict__ h0P,
                   const float* __restrict__ WihP,
                   const float* __restrict__ WhhP,
                   float* __restrict__ C, int B)
{
    __shared__ __align__(16) float As[2][128][36];
    __shared__ __align__(16) float Bs[2][128][36];

    const int row0 = blockIdx.y * 128;
    const int col0 = blockIdx.x * 128;
    const int lr   = threadIdx.x >> 1;

    float acc[2][8][4];
#pragma unroll
    for (int mi = 0; mi < 2; mi++)
#pragma unroll
        for (int ni = 0; ni < 8; ni++)
#pragma unroll
            for (int r = 0; r < 4; r++) acc[mi][ni][r] = 0.f;

    const int gr = row0 + lr;
    tc_mainloop(numP + (size_t)gr * ED, true,
                WihP + 7680 + (size_t)(col0 + lr) * IN_DIM, 4, As, Bs, acc);
    tc_mainloop(h0P + (size_t)gr * LH, true,
                WhhP + (size_t)(col0 + lr) * LH, 4, As, Bs, acc);

    tc_epilogue(acc, C, NG, row0, col0, B);
}

// ---------------------------------------------------------------------------
// Tables GEMM: z = 0..11 ability slots, z = 12..59 move slots.
// ---------------------------------------------------------------------------
__global__ __launch_bounds__(256, 2)
void tc_gemm_tables(const float* __restrict__ abP,
                    const float* __restrict__ mvP,
                    const float* __restrict__ WihP,
                    float* __restrict__ tabAb,
                    float* __restrict__ tabMv)
{
    const int z = blockIdx.z;
    const float* A; const float* W; float* C; int M;
    if (z < 12) {
        A = abP; M = N_AB;
        W = WihP + (size_t)z * ED;
        C = tabAb + (size_t)z * N_AB * NG;
    } else {
        const int zz = z - 12;
        A = mvP; M = N_MV;
        W = WihP + 1536 + (size_t)zz * ED;
        C = tabMv + (size_t)zz * N_MV * NG;
    }
    const int row0 = blockIdx.y * 128;
    if (row0 >= M) return;
    const int col0 = blockIdx.x * 128;

    __shared__ __align__(16) float As[2][128][36];
    __shared__ __align__(16) float Bs[2][128][36];

    float acc[2][8][4];
#pragma unroll
    for (int mi = 0; mi < 2; mi++)
#pragma unroll
        for (int ni = 0; ni < 8; ni++)
#pragma unroll
            for (int r = 0; r < 4; r++) acc[mi][ni][r] = 0.f;

    const int lr = threadIdx.x >> 1;
    const int gr = row0 + lr;
    const bool okA = (gr < M);
    tc_mainloop(A + (size_t)(okA ? gr : 0) * ED, okA,
                W + (size_t)(col0 + lr) * IN_DIM, 4, As, Bs, acc);

    tc_epilogue(acc, C, NG, row0, col0, M);
}

// ---------------------------------------------------------------------------
// Num projection (K=84), fp32 SIMT; output tf32-rounded + permuted.
// ---------------------------------------------------------------------------
#define BM 64
#define BN 64
#define BK 32

__global__ void gemm_nt_kernel(const float* __restrict__ A, int lda,
                               const float* __restrict__ W, int ldw,
                               float* __restrict__ C, int ldc, int M,
                               int N, int K,
                               const float* __restrict__ bias)
{
    __shared__ float As[BK][BM + 1];
    __shared__ float Bs[BK][BN + 1];

    const int row0 = blockIdx.y * BM;
    const int col0 = blockIdx.x * BN;
    const int t  = threadIdx.x;
    const int tx = t & 15;
    const int ty = t >> 4;

    float acc[4][4];
#pragma unroll
    for (int i = 0; i < 4; i++)
#pragma unroll
        for (int j = 0; j < 4; j++) acc[i][j] = 0.f;

    const int lm = t >> 2;
    const int ks = (t & 3) * 8;

    for (int k0 = 0; k0 < K; k0 += BK) {
        {
            const int gr = row0 + lm;
            const bool rok = (gr < M);
            const size_t base = (size_t)gr * lda + k0 + ks;
#pragma unroll
            for (int i = 0; i < 8; i++) {
                const int k = k0 + ks + i;
                As[ks + i][lm] = (rok && k < K) ? A[base + i] : 0.f;
            }
        }
        {
            const int gc = col0 + lm;
            const bool cok = (gc < N);
            const size_t base = (size_t)gc * ldw + k0 + ks;
#pragma unroll
            for (int i = 0; i < 8; i++) {
                const int k = k0 + ks + i;
                Bs[ks + i][lm] = (cok && k < K) ? W[base + i] : 0.f;
            }
        }
        __syncthreads();

#pragma unroll
        for (int kk = 0; kk < BK; kk++) {
            float a[4], b[4];
#pragma unroll
            for (int i = 0; i < 4; i++) a[i] = As[kk][ty * 4 + i];
#pragma unroll
            for (int i = 0; i < 4; i++) b[i] = Bs[kk][tx * 4 + i];
#pragma unroll
            for (int i = 0; i < 4; i++)
#pragma unroll
                for (int j = 0; j < 4; j++)
                    acc[i][j] += a[i] * b[j];
        }
        __syncthreads();
    }

#pragma unroll
    for (int i = 0; i < 4; i++) {
        const int r = row0 + ty * 4 + i;
        if (r >= M) continue;
#pragma unroll
        for (int j = 0; j < 4; j++) {
            const int c = col0 + tx * 4 + j;
            if (c >= N) continue;
            float v = acc[i][j];
            if (bias) v += bias[c];
            C[(size_t)r * ldc + perm32(c)] = __uint_as_float(f2tf32(v));
        }
    }
}

// ---------------------------------------------------------------------------
// Fused tail: one 128-thread block per batch row; float4 gathers.
// ---------------------------------------------------------------------------
__global__ __launch_bounds__(128, 8)
void fused_tail_v2(const int* __restrict__ ability_ids,
                   const int* __restrict__ move_ids,
                   const float* __restrict__ c0,
                   const float* __restrict__ mask,
                   const float* __restrict__ bih,
                   const float* __restrict__ bhh,
                   const float* __restrict__ W1,
                   const float* __restrict__ b1,
                   const float* __restrict__ W2,
                   const float* __restrict__ b2,
                   const float* __restrict__ Wa,
                   const float* __restrict__ ba,
                   float* __restrict__ out, int B)
{
    __shared__ int   s_aid[12];
    __shared__ int   s_mid[48];
    __shared__ __align__(16) float s_g[NG];
    __shared__ float s_h1[LH];
    __shared__ float s_t1[HD];
    __shared__ float s_feat[ED];
    __shared__ float s_logits[9];

    const int b = blockIdx.x;
    const int j = threadIdx.x;          // 0..127

    if (j < 12)      s_aid[j]      = ability_ids[b * 12 + j];
    else if (j < 60) s_mid[j - 12] = move_ids[b * 48 + (j - 12)];
    __syncthreads();

    {
        const size_t c4 = (size_t)4 * j;
        float4 acc = *(const float4*)(g_gates + (size_t)b * NG + c4);
        const float4 bi = *(const float4*)(bih + c4);
        const float4 bh = *(const float4*)(bhh + c4);
        acc.x += bi.x + bh.x; acc.y += bi.y + bh.y;
        acc.z += bi.z + bh.z; acc.w += bi.w + bh.w;
#pragma unroll
        for (int s = 0; s < 12; s++) {
            const float4 v = *(const float4*)(
                g_tab_ab + ((size_t)(s * N_AB + s_aid[s])) * NG + c4);
            acc.x += v.x; acc.y += v.y; acc.z += v.z; acc.w += v.w;
        }
#pragma unroll
        for (int s = 0; s < 48; s++) {
            const float4 v = *(const float4*)(
                g_tab_mv + ((size_t)(s * N_MV + s_mid[s])) * NG + c4);
            acc.x += v.x; acc.y += v.y; acc.z += v.z; acc.w += v.w;
        }
        *(float4*)(s_g + c4) = acc;
    }
    __syncthreads();

    {
        const float iv = 1.f / (1.f + expf(-s_g[j]));
        const float fv = 1.f / (1.f + expf(-s_g[LH + j]));
        const float gv = tanhf(s_g[2 * LH + j]);
        const float ov = 1.f / (1.f + expf(-s_g[3 * LH + j]));
        const float c1 = fv * c0[(size_t)b * LH + j] + iv * gv;
        const float h1 = ov * tanhf(c1);
        s_h1[j] = h1;
        out[(size_t)B * 9 + (size_t)b * LH + j] = h1;
        out[(size_t)B * 9 + (size_t)B * LH + (size_t)b * LH + j] = c1;
    }
    __syncthreads();

    if (j < HD) {
        float a = b1[j];
#pragma unroll
        for (int t = 0; t < LH; t++) a += W1[j * LH + t] * s_h1[t];
        s_t1[j] = fmaxf(a, 0.f);
    }
    __syncthreads();

    {
        float a = b2[j];
#pragma unroll
        for (int t = 0; t < HD; t++) a += W2[j * HD + t] * s_t1[t];
        s_feat[j] = a;
    }
    __syncthreads();

    if (j < 9) {
        float a = ba[j];
#pragma unroll
        for (int t = 0; t < ED; t++) a += Wa[j * ED + t] * s_feat[t];
        s_logits[j] = a;
    }
    __syncthreads();

    if (j == 0) {
        float mx = s_logits[0];
#pragma unroll
        for (int a = 1; a < 9; a++) mx = fmaxf(mx, s_logits[a]);
        float p[9], sum = 0.f;
#pragma unroll
        for (int a = 0; a < 9; a++) { p[a] = expf(s_logits[a] - mx); sum += p[a]; }
        float pm[9], msum = 0.f;
#pragma unroll
        for (int a = 0; a < 9; a++) {
            p[a] /= sum;
            pm[a] = p[a] * mask[(size_t)b * 9 + a];
            msum += pm[a];
        }
#pragma unroll
        for (int a = 0; a < 9; a++)
            out[(size_t)b * 9 + a] = (msum > 0.f) ? (pm[a] / msum) : p[a];
    }
}

// ---------------------------------------------------------------------------
extern "C" void kernel_launch(void* const* d_in, const int* in_sizes, int n_in,
                              void* d_out, int out_size)
{
    const int*   ability_ids = (const int*)  d_in[0];
    const int*   move_ids    = (const int*)  d_in[1];
    const float* numerical   = (const float*)d_in[2];
    const float* mask        = (const float*)d_in[3];
    const float* h0          = (const float*)d_in[4];
    const float* c0          = (const float*)d_in[5];
    const float* ability_emb = (const float*)d_in[6];
    const float* move_emb    = (const float*)d_in[7];
    const float* num_W       = (const float*)d_in[8];
    const float* num_b       = (const float*)d_in[9];
    const float* Wih         = (const float*)d_in[10];
    const float* Whh         = (const float*)d_in[11];
    const float* bih         = (const float*)d_in[12];
    const float* bhh         = (const float*)d_in[13];
    const float* W1          = (const float*)d_in[14];
    const float* b1          = (const float*)d_in[15];
    const float* W2          = (const float*)d_in[16];
    const float* b2          = (const float*)d_in[17];
    const float* Wa          = (const float*)d_in[18];
    const float* ba          = (const float*)d_in[19];

    const int B = in_sizes[0] / 12;   // 4096

    float *p_num, *p_gates, *p_tab_ab, *p_tab_mv;
    float *p_Wih, *p_Whh, *p_ab, *p_mv, *p_h0;
    cudaGetSymbolAddress((void**)&p_num,    g_num);
    cudaGetSymbolAddress((void**)&p_gates,  g_gates);
    cudaGetSymbolAddress((void**)&p_tab_ab, g_tab_ab);
    cudaGetSymbolAddress((void**)&p_tab_mv, g_tab_mv);
    cudaGetSymbolAddress((void**)&p_Wih,    g_Wih_t);
    cudaGetSymbolAddress((void**)&p_Whh,    g_Whh_t);
    cudaGetSymbolAddress((void**)&p_ab,     g_abemb_t);
    cudaGetSymbolAddress((void**)&p_mv,     g_mvemb_t);
    cudaGetSymbolAddress((void**)&p_h0,     g_h0_t);

    // 0) tf32-round + permute all TC GEMM operands (one kernel)
    const int n0 = NG * IN_DIM / 4;
    const int n1 = NG * LH / 4;
    const int n2 = N_AB * ED / 4;
    const int n3 = N_MV * ED / 4;
    const int n4 = B * LH / 4;
    const int ntot = n0 + n1 + n2 + n3 + n4;
    cvt_perm5<<<(ntot + 255) / 256, 256>>>(
        (const float4*)Wih, p_Wih, n0,
        (const float4*)Whh, p_Whh, n1,
        (const float4*)ability_emb, p_ab, n2,
        (const float4*)move_emb, p_mv, n3,
        (const float4*)h0, p_h0, n4);

    // 1) num = tf32perm(numerical @ num_W^T + num_b)  [B,128], K=84 (SIMT)
    gemm_nt_kernel<<<dim3(2, (B + BM - 1) / BM, 1), 256>>>(
        numerical, 84, num_W, 84, p_num, ED, B, ED, 84, num_b);

    // 2) gates = num @ Wih_num^T + h0 @ Whh^T         [B,512] (one TC kernel)
    tc_gemm_gates<<<dim3(NG / 128, B / 128, 1), 256>>>(
        p_num, p_h0, p_Wih, p_Whh, p_gates, B);

    // 3) all 60 per-slot tables in one launch
    tc_gemm_tables<<<dim3(NG / 128, 8, 60), 256>>>(
        p_ab, p_mv, p_Wih, p_tab_ab, p_tab_mv);

    // 4) fused gather + LSTM + MLP + masked softmax
    fused_tail_v2<<<B, 128>>>(ability_ids, move_ids, c0, mask,
                              bih, bhh, W1, b1, W2, b2, Wa, ba,
                              (float*)d_out, B);
}

// round 14
// speedup vs baseline: 3.8381x; 2.2213x over previous
#include <cuda_runtime.h>
#include <math.h>
#include <stdint.h>

// Problem constants
#define ED 128
#define LH 128
#define HD 64
#define NG 512            // 4*LH
#define N_AB 300
#define N_MV 900
#define MAXB 4096
#define IN_DIM 7808

// -------- scratch (device globals; no allocations allowed) --------
__device__ float g_num[MAXB * ED];                  // tf32+perm num projection [B,128]
__device__ float g_gates[(size_t)MAXB * NG];        // gates partial (num + hh) [B,512]
__device__ float g_tab_ab[12 * N_AB * NG];          // per-slot ability tables
__device__ float g_tab_mv[48 * N_MV * NG];          // per-slot move tables
__device__ float g_h1[MAXB * LH];                   // LSTM hidden out
__device__ float g_t1[MAXB * HD];                   // relu(h1 W1^T + b1)
__device__ float g_feat[MAXB * ED];                 // t1 W2^T + b2
// tf32-rounded + column-permuted copies of GEMM operands
__device__ float g_Wih_t[(size_t)NG * IN_DIM];
__device__ float g_Whh_t[NG * LH];
__device__ float g_abemb_t[N_AB * ED];
__device__ float g_mvemb_t[N_MV * ED];
__device__ float g_h0_t[MAXB * LH];

__device__ __forceinline__ uint32_t f2tf32(float x) {
    uint32_t r;
    asm("cvt.rna.tf32.f32 %0, %1;" : "=r"(r) : "f"(x));
    return r;
}

__device__ __forceinline__ void cp_async16(void* smem, const void* gmem, bool valid) {
    uint32_t s = (uint32_t)__cvta_generic_to_shared(smem);
    int sz = valid ? 16 : 0;
    asm volatile("cp.async.cg.shared.global [%0], [%1], 16, %2;"
                 :: "r"(s), "l"(gmem), "r"(sz));
}

// column permutation within each 32-col group: c -> (c&3)*8 + (c>>2)
__device__ __forceinline__ int perm32(int c) {
    return (c & ~31) | (((c & 3) << 3) | ((c & 31) >> 2));
}

// ---------------------------------------------------------------------------
// Fused tf32-round + permute pass over 5 buffers (float4-indexed lengths).
// ---------------------------------------------------------------------------
__global__ void cvt_perm5(const float4* __restrict__ s0, float* __restrict__ d0, int n0,
                          const float4* __restrict__ s1, float* __restrict__ d1, int n1,
                          const float4* __restrict__ s2, float* __restrict__ d2, int n2,
                          const float4* __restrict__ s3, float* __restrict__ d3, int n3,
                          const float4* __restrict__ s4, float* __restrict__ d4, int n4)
{
    int i = blockIdx.x * blockDim.x + threadIdx.x;
    const float4* s; float* d; int local = i;
    if      (local <  n0) { s = s0; d = d0; }
    else if ((local -= n0) < n1) { s = s1; d = d1; }
    else if ((local -= n1) < n2) { s = s2; d = d2; }
    else if ((local -= n2) < n3) { s = s3; d = d3; }
    else if ((local -= n3) < n4) { s = s4; d = d4; }
    else return;

    float4 v = s[local];
    const int base = (local * 4) & ~31;   // 32-col group base
    const int m = local & 7;              // c>>2 within group
    d[base +  0 + m] = __uint_as_float(f2tf32(v.x));
    d[base +  8 + m] = __uint_as_float(f2tf32(v.y));
    d[base + 16 + m] = __uint_as_float(f2tf32(v.z));
    d[base + 24 + m] = __uint_as_float(f2tf32(v.w));
}

// ---------------------------------------------------------------------------
// Tensor-core mainloop over permuted operands. CTA 128x128, BK=32,
// 256 threads (8 warps: 4 in M x 2 in N), double-buffered cp.async.
// ---------------------------------------------------------------------------
__device__ __forceinline__ void tc_mainloop(
    const float* __restrict__ srcA, bool okA,
    const float* __restrict__ srcW,
    int tiles,
    float (*As)[128][36], float (*Bs)[128][36],
    float (&acc)[2][8][4])
{
    const int t    = threadIdx.x;
    const int lane = t & 31;
    const int wid  = t >> 5;
    const int wm   = wid & 3;
    const int wn   = wid >> 2;
    const int g    = lane >> 2;
    const int q    = lane & 3;
    const int lr   = t >> 1;
    const int lq   = t & 1;

#pragma unroll
    for (int it = 0; it < 4; it++) {
        const int f4 = lq + it * 2;
        cp_async16(&As[0][lr][f4 * 4], srcA + f4 * 4, okA);
        cp_async16(&Bs[0][lr][f4 * 4], srcW + f4 * 4, true);
    }
    asm volatile("cp.async.commit_group;");

    for (int tt = 0; tt < tiles; tt++) {
        const int buf = tt & 1;
        if (tt + 1 < tiles) {
            const int nb = (tt + 1) & 1;
            const int k0 = (tt + 1) * 32;
#pragma unroll
            for (int it = 0; it < 4; it++) {
                const int f4 = lq + it * 2;
                cp_async16(&As[nb][lr][f4 * 4], srcA + k0 + f4 * 4, okA);
                cp_async16(&Bs[nb][lr][f4 * 4], srcW + k0 + f4 * 4, true);
            }
            asm volatile("cp.async.commit_group;");
            asm volatile("cp.async.wait_group 1;");
        } else {
            asm volatile("cp.async.wait_group 0;");
        }
        __syncthreads();

        float aG[2][8], aG8[2][8];
#pragma unroll
        for (int mi = 0; mi < 2; mi++) {
            const int r0 = wm * 32 + mi * 16 + g;
            const float4 x0 = *(const float4*)&As[buf][r0][q * 8];
            const float4 x1 = *(const float4*)&As[buf][r0][q * 8 + 4];
            const float4 y0 = *(const float4*)&As[buf][r0 + 8][q * 8];
            const float4 y1 = *(const float4*)&As[buf][r0 + 8][q * 8 + 4];
            aG[mi][0] = x0.x; aG[mi][1] = x0.y; aG[mi][2] = x0.z; aG[mi][3] = x0.w;
            aG[mi][4] = x1.x; aG[mi][5] = x1.y; aG[mi][6] = x1.z; aG[mi][7] = x1.w;
            aG8[mi][0] = y0.x; aG8[mi][1] = y0.y; aG8[mi][2] = y0.z; aG8[mi][3] = y0.w;
            aG8[mi][4] = y1.x; aG8[mi][5] = y1.y; aG8[mi][6] = y1.z; aG8[mi][7] = y1.w;
        }

#pragma unroll
        for (int ni = 0; ni < 8; ni++) {
            const int c = wn * 64 + ni * 8 + g;
            const float4 b0 = *(const float4*)&Bs[buf][c][q * 8];
            const float4 b1 = *(const float4*)&Bs[buf][c][q * 8 + 4];
            float bb[8] = {b0.x, b0.y, b0.z, b0.w, b1.x, b1.y, b1.z, b1.w};
#pragma unroll
            for (int kk = 0; kk < 4; kk++) {
#pragma unroll
                for (int mi = 0; mi < 2; mi++) {
                    asm volatile(
                        "mma.sync.aligned.m16n8k8.row.col.f32.tf32.tf32.f32 "
                        "{%0,%1,%2,%3}, {%4,%5,%6,%7}, {%8,%9}, {%0,%1,%2,%3};"
                        : "+f"(acc[mi][ni][0]), "+f"(acc[mi][ni][1]),
                          "+f"(acc[mi][ni][2]), "+f"(acc[mi][ni][3])
                        : "r"(__float_as_uint(aG[mi][2 * kk])),
                          "r"(__float_as_uint(aG8[mi][2 * kk])),
                          "r"(__float_as_uint(aG[mi][2 * kk + 1])),
                          "r"(__float_as_uint(aG8[mi][2 * kk + 1])),
                          "r"(__float_as_uint(bb[2 * kk])),
                          "r"(__float_as_uint(bb[2 * kk + 1])));
                }
            }
        }
        __syncthreads();
    }
}

__device__ __forceinline__ void tc_epilogue(float (&acc)[2][8][4],
                                            float* __restrict__ Cz, int ldc,
                                            int row0, int col0, int M)
{
    const int t    = threadIdx.x;
    const int lane = t & 31;
    const int wid  = t >> 5;
    const int wm   = wid & 3;
    const int wn   = wid >> 2;
    const int g    = lane >> 2;
    const int q    = lane & 3;

#pragma unroll
    for (int mi = 0; mi < 2; mi++) {
        const int rA = row0 + wm * 32 + mi * 16 + g;
        const int rB = rA + 8;
#pragma unroll
        for (int ni = 0; ni < 8; ni++) {
            const int c = col0 + wn * 64 + ni * 8 + q * 2;
            if (rA < M)
                *(float2*)(Cz + (size_t)rA * ldc + c) =
                    make_float2(acc[mi][ni][0], acc[mi][ni][1]);
            if (rB < M)
                *(float2*)(Cz + (size_t)rB * ldc + c) =
                    make_float2(acc[mi][ni][2], acc[mi][ni][3]);
        }
    }
}

// ---------------------------------------------------------------------------
// Gates GEMM: gates = num @ Wih_num^T + h0 @ Whh^T  (one kernel)
// ---------------------------------------------------------------------------
__global__ __launch_bounds__(256, 2)
void tc_gemm_gates(const float* __restrict__ numP,
                   const float* __restrict__ h0P,
                   const float* __restrict__ WihP,
                   const float* __restrict__ WhhP,
                   float* __restrict__ C, int B)
{
    __shared__ __align__(16) float As[2][128][36];
    __shared__ __align__(16) float Bs[2][128][36];

    const int row0 = blockIdx.y * 128;
    const int col0 = blockIdx.x * 128;
    const int lr   = threadIdx.x >> 1;

    float acc[2][8][4];
#pragma unroll
    for (int mi = 0; mi < 2; mi++)
#pragma unroll
        for (int ni = 0; ni < 8; ni++)
#pragma unroll
            for (int r = 0; r < 4; r++) acc[mi][ni][r] = 0.f;

    const int gr = row0 + lr;
    tc_mainloop(numP + (size_t)gr * ED, true,
                WihP + 7680 + (size_t)(col0 + lr) * IN_DIM, 4, As, Bs, acc);
    tc_mainloop(h0P + (size_t)gr * LH, true,
                WhhP + (size_t)(col0 + lr) * LH, 4, As, Bs, acc);

    tc_epilogue(acc, C, NG, row0, col0, B);
}

// ---------------------------------------------------------------------------
// Tables GEMM: z = 0..11 ability slots, z = 12..59 move slots.
// ---------------------------------------------------------------------------
__global__ __launch_bounds__(256, 2)
void tc_gemm_tables(const float* __restrict__ abP,
                    const float* __restrict__ mvP,
                    const float* __restrict__ WihP,
                    float* __restrict__ tabAb,
                    float* __restrict__ tabMv)
{
    const int z = blockIdx.z;
    const float* A; const float* W; float* C; int M;
    if (z < 12) {
        A = abP; M = N_AB;
        W = WihP + (size_t)z * ED;
        C = tabAb + (size_t)z * N_AB * NG;
    } else {
        const int zz = z - 12;
        A = mvP; M = N_MV;
        W = WihP + 1536 + (size_t)zz * ED;
        C = tabMv + (size_t)zz * N_MV * NG;
    }
    const int row0 = blockIdx.y * 128;
    if (row0 >= M) return;
    const int col0 = blockIdx.x * 128;

    __shared__ __align__(16) float As[2][128][36];
    __shared__ __align__(16) float Bs[2][128][36];

    float acc[2][8][4];
#pragma unroll
    for (int mi = 0; mi < 2; mi++)
#pragma unroll
        for (int ni = 0; ni < 8; ni++)
#pragma unroll
            for (int r = 0; r < 4; r++) acc[mi][ni][r] = 0.f;

    const int lr = threadIdx.x >> 1;
    const int gr = row0 + lr;
    const bool okA = (gr < M);
    tc_mainloop(A + (size_t)(okA ? gr : 0) * ED, okA,
                W + (size_t)(col0 + lr) * IN_DIM, 4, As, Bs, acc);

    tc_epilogue(acc, C, NG, row0, col0, M);
}

// ---------------------------------------------------------------------------
// SIMT GEMM (64x64x32 tiles). flags: bit0 = tf32-round+perm output (num path),
// bit1 = relu.
// ---------------------------------------------------------------------------
#define BM 64
#define BN 64
#define BK 32

__global__ void gemm_nt_kernel(const float* __restrict__ A, int lda,
                               const float* __restrict__ W, int ldw,
                               float* __restrict__ C, int ldc, int M,
                               int N, int K,
                               const float* __restrict__ bias, int flags)
{
    __shared__ float As[BK][BM + 1];
    __shared__ float Bs[BK][BN + 1];

    const int row0 = blockIdx.y * BM;
    const int col0 = blockIdx.x * BN;
    const int t  = threadIdx.x;
    const int tx = t & 15;
    const int ty = t >> 4;

    float acc[4][4];
#pragma unroll
    for (int i = 0; i < 4; i++)
#pragma unroll
        for (int j = 0; j < 4; j++) acc[i][j] = 0.f;

    const int lm = t >> 2;
    const int ks = (t & 3) * 8;

    for (int k0 = 0; k0 < K; k0 += BK) {
        {
            const int gr = row0 + lm;
            const bool rok = (gr < M);
            const size_t base = (size_t)gr * lda + k0 + ks;
#pragma unroll
            for (int i = 0; i < 8; i++) {
                const int k = k0 + ks + i;
                As[ks + i][lm] = (rok && k < K) ? A[base + i] : 0.f;
            }
        }
        {
            const int gc = col0 + lm;
            const bool cok = (gc < N);
            const size_t base = (size_t)gc * ldw + k0 + ks;
#pragma unroll
            for (int i = 0; i < 8; i++) {
                const int k = k0 + ks + i;
                Bs[ks + i][lm] = (cok && k < K) ? W[base + i] : 0.f;
            }
        }
        __syncthreads();

#pragma unroll
        for (int kk = 0; kk < BK; kk++) {
            float a[4], b[4];
#pragma unroll
            for (int i = 0; i < 4; i++) a[i] = As[kk][ty * 4 + i];
#pragma unroll
            for (int i = 0; i < 4; i++) b[i] = Bs[kk][tx * 4 + i];
#pragma unroll
            for (int i = 0; i < 4; i++)
#pragma unroll
                for (int j = 0; j < 4; j++)
                    acc[i][j] += a[i] * b[j];
        }
        __syncthreads();
    }

#pragma unroll
    for (int i = 0; i < 4; i++) {
        const int r = row0 + ty * 4 + i;
        if (r >= M) continue;
#pragma unroll
        for (int j = 0; j < 4; j++) {
            const int c = col0 + tx * 4 + j;
            if (c >= N) continue;
            float v = acc[i][j];
            if (bias) v += bias[c];
            if (flags & 2) v = fmaxf(v, 0.f);
            if (flags & 1)
                C[(size_t)r * ldc + perm32(c)] = __uint_as_float(f2tf32(v));
            else
                C[(size_t)r * ldc + c] = v;
        }
    }
}

// ---------------------------------------------------------------------------
// Gather + LSTM only: one 128-thread block per batch row; float4 gathers.
// Writes h1,c1 to out and h1 to g_h1 for the MLP head.
// ---------------------------------------------------------------------------
__global__ __launch_bounds__(128, 12)
void gather_lstm_kernel(const int* __restrict__ ability_ids,
                        const int* __restrict__ move_ids,
                        const float* __restrict__ c0,
                        const float* __restrict__ bih,
                        const float* __restrict__ bhh,
                        float* __restrict__ out, int B)
{
    __shared__ int   s_aid[12];
    __shared__ int   s_mid[48];
    __shared__ __align__(16) float s_g[NG];

    const int b = blockIdx.x;
    const int j = threadIdx.x;          // 0..127

    if (j < 12)      s_aid[j]      = ability_ids[b * 12 + j];
    else if (j < 60) s_mid[j - 12] = move_ids[b * 48 + (j - 12)];
    __syncthreads();

    {
        const size_t c4 = (size_t)4 * j;
        float4 acc = *(const float4*)(g_gates + (size_t)b * NG + c4);
        const float4 bi = *(const float4*)(bih + c4);
        const float4 bh = *(const float4*)(bhh + c4);
        acc.x += bi.x + bh.x; acc.y += bi.y + bh.y;
        acc.z += bi.z + bh.z; acc.w += bi.w + bh.w;
#pragma unroll
        for (int s = 0; s < 12; s++) {
            const float4 v = *(const float4*)(
                g_tab_ab + ((size_t)(s * N_AB + s_aid[s])) * NG + c4);
            acc.x += v.x; acc.y += v.y; acc.z += v.z; acc.w += v.w;
        }
#pragma unroll
        for (int s = 0; s < 48; s++) {
            const float4 v = *(const float4*)(
                g_tab_mv + ((size_t)(s * N_MV + s_mid[s])) * NG + c4);
            acc.x += v.x; acc.y += v.y; acc.z += v.z; acc.w += v.w;
        }
        *(float4*)(s_g + c4) = acc;
    }
    __syncthreads();

    {
        const float iv = 1.f / (1.f + expf(-s_g[j]));
        const float fv = 1.f / (1.f + expf(-s_g[LH + j]));
        const float gv = tanhf(s_g[2 * LH + j]);
        const float ov = 1.f / (1.f + expf(-s_g[3 * LH + j]));
        const float c1 = fv * c0[(size_t)b * LH + j] + iv * gv;
        const float h1 = ov * tanhf(c1);
        g_h1[(size_t)b * LH + j] = h1;
        out[(size_t)B * 9 + (size_t)b * LH + j] = h1;
        out[(size_t)B * 9 + (size_t)B * LH + (size_t)b * LH + j] = c1;
    }
}

// ---------------------------------------------------------------------------
// Logits + softmax + masked renorm: one warp per batch row.
// ---------------------------------------------------------------------------
__global__ __launch_bounds__(256, 8)
void logits_softmax_kernel(const float* __restrict__ Wa,
                           const float* __restrict__ ba,
                           const float* __restrict__ mask,
                           float* __restrict__ out, int B)
{
    const int warp = threadIdx.x >> 5;
    const int lane = threadIdx.x & 31;
    const int b = blockIdx.x * 8 + warp;
    if (b >= B) return;
    const float* f = g_feat + (size_t)b * ED;

    float lg[9];
#pragma unroll
    for (int a = 0; a < 9; a++) {
        float p = 0.f;
#pragma unroll
        for (int t = lane; t < ED; t += 32) p += f[t] * Wa[a * ED + t];
#pragma unroll
        for (int o = 16; o > 0; o >>= 1) p += __shfl_xor_sync(0xffffffff, p, o);
        lg[a] = p + ba[a];
    }
    if (lane == 0) {
        float mx = lg[0];
#pragma unroll
        for (int a = 1; a < 9; a++) mx = fmaxf(mx, lg[a]);
        float pp[9], sum = 0.f;
#pragma unroll
        for (int a = 0; a < 9; a++) { pp[a] = expf(lg[a] - mx); sum += pp[a]; }
        float pm[9], msum = 0.f;
#pragma unroll
        for (int a = 0; a < 9; a++) {
            pp[a] /= sum;
            pm[a] = pp[a] * mask[(size_t)b * 9 + a];
            msum += pm[a];
        }
#pragma unroll
        for (int a = 0; a < 9; a++)
            out[(size_t)b * 9 + a] = (msum > 0.f) ? (pm[a] / msum) : pp[a];
    }
}

// ---------------------------------------------------------------------------
extern "C" void kernel_launch(void* const* d_in, const int* in_sizes, int n_in,
                              void* d_out, int out_size)
{
    const int*   ability_ids = (const int*)  d_in[0];
    const int*   move_ids    = (const int*)  d_in[1];
    const float* numerical   = (const float*)d_in[2];
    const float* mask        = (const float*)d_in[3];
    const float* h0          = (const float*)d_in[4];
    const float* c0          = (const float*)d_in[5];
    const float* ability_emb = (const float*)d_in[6];
    const float* move_emb    = (const float*)d_in[7];
    const float* num_W       = (const float*)d_in[8];
    const float* num_b       = (const float*)d_in[9];
    const float* Wih         = (const float*)d_in[10];
    const float* Whh         = (const float*)d_in[11];
    const float* bih         = (const float*)d_in[12];
    const float* bhh         = (const float*)d_in[13];
    const float* W1          = (const float*)d_in[14];
    const float* b1          = (const float*)d_in[15];
    const float* W2          = (const float*)d_in[16];
    const float* b2          = (const float*)d_in[17];
    const float* Wa          = (const float*)d_in[18];
    const float* ba          = (const float*)d_in[19];

    const int B = in_sizes[0] / 12;   // 4096

    float *p_num, *p_gates, *p_tab_ab, *p_tab_mv;
    float *p_Wih, *p_Whh, *p_ab, *p_mv, *p_h0, *p_h1, *p_t1, *p_feat;
    cudaGetSymbolAddress((void**)&p_num,    g_num);
    cudaGetSymbolAddress((void**)&p_gates,  g_gates);
    cudaGetSymbolAddress((void**)&p_tab_ab, g_tab_ab);
    cudaGetSymbolAddress((void**)&p_tab_mv, g_tab_mv);
    cudaGetSymbolAddress((void**)&p_Wih,    g_Wih_t);
    cudaGetSymbolAddress((void**)&p_Whh,    g_Whh_t);
    cudaGetSymbolAddress((void**)&p_ab,     g_abemb_t);
    cudaGetSymbolAddress((void**)&p_mv,     g_mvemb_t);
    cudaGetSymbolAddress((void**)&p_h0,     g_h0_t);
    cudaGetSymbolAddress((void**)&p_h1,     g_h1);
    cudaGetSymbolAddress((void**)&p_t1,     g_t1);
    cudaGetSymbolAddress((void**)&p_feat,   g_feat);

    // 0) tf32-round + permute all TC GEMM operands (one kernel)
    const int n0 = NG * IN_DIM / 4;
    const int n1 = NG * LH / 4;
    const int n2 = N_AB * ED / 4;
    const int n3 = N_MV * ED / 4;
    const int n4 = B * LH / 4;
    const int ntot = n0 + n1 + n2 + n3 + n4;
    cvt_perm5<<<(ntot + 255) / 256, 256>>>(
        (const float4*)Wih, p_Wih, n0,
        (const float4*)Whh, p_Whh, n1,
        (const float4*)ability_emb, p_ab, n2,
        (const float4*)move_emb, p_mv, n3,
        (const float4*)h0, p_h0, n4);

    // 1) num = tf32perm(numerical @ num_W^T + num_b)  [B,128], K=84 (SIMT)
    gemm_nt_kernel<<<dim3(2, (B + BM - 1) / BM, 1), 256>>>(
        numerical, 84, num_W, 84, p_num, ED, B, ED, 84, num_b, 1);

    // 2) gates = num @ Wih_num^T + h0 @ Whh^T         [B,512] (one TC kernel)
    tc_gemm_gates<<<dim3(NG / 128, B / 128, 1), 256>>>(
        p_num, p_h0, p_Wih, p_Whh, p_gates, B);

    // 3) all 60 per-slot tables in one launch
    tc_gemm_tables<<<dim3(NG / 128, 8, 60), 256>>>(
        p_ab, p_mv, p_Wih, p_tab_ab, p_tab_mv);

    // 4) gather + LSTM (memory-bound part of the tail)
    gather_lstm_kernel<<<B, 128>>>(ability_ids, move_ids, c0,
                                   bih, bhh, (float*)d_out, B);

    // 5) t1 = relu(h1 @ W1^T + b1)     [B,64], K=128
    gemm_nt_kernel<<<dim3(1, (B + BM - 1) / BM, 1), 256>>>(
        p_h1, LH, W1, LH, p_t1, HD, B, HD, LH, b1, 2);

    // 6) feat = t1 @ W2^T + b2         [B,128], K=64
    gemm_nt_kernel<<<dim3(2, (B + BM - 1) / BM, 1), 256>>>(
        p_t1, HD, W2, HD, p_feat, ED, B, ED, HD, b2, 0);

    // 7) logits + softmax + masked renorm (warp per row)
    logits_softmax_kernel<<<(B + 7) / 8, 256>>>(Wa, ba, mask, (float*)d_out, B);
}